// round 2
// baseline (speedup 1.0000x reference)
#include <cuda_runtime.h>

#define N_ROWS 8192
#define S_ROWS 4096
#define C_DIM  256

// Scratch (static device arrays — no allocation at runtime)
__device__ float g_Sn[N_ROWS * C_DIM];
__device__ float g_Fn[N_ROWS * C_DIM];
__device__ float g_Vn[S_ROWS * C_DIM];
__device__ float g_Kn[S_ROWS * C_DIM];

// -------- fast exp on FMA pipe (avoids MUFU.EX2 throughput wall) --------
// Valid for x in [-80, 80]; here x ∈ [-11, 0]. |rel err| ~1e-7.
__device__ __forceinline__ float fexp(float x) {
    x = fmaxf(x, -80.0f);
    float z = fmaf(x, 1.4426950408889634f, 12582912.0f); // round-to-nearest int trick
    float n = z - 12582912.0f;                            // n = rint(x * log2e)
    float r = fmaf(n, -0.69314718055994531f, x);          // r = x - n*ln2, |r| <= 0.347
    float p = 1.3888889e-3f;                              // 1/720
    p = fmaf(p, r, 8.3333333e-3f);                        // 1/120
    p = fmaf(p, r, 4.1666667e-2f);                        // 1/24
    p = fmaf(p, r, 1.6666667e-1f);                        // 1/6
    p = fmaf(p, r, 0.5f);
    p = fmaf(p, r, 1.0f);
    p = fmaf(p, r, 1.0f);
    int e = (int)n;
    return p * __int_as_float((e + 127) << 23);
}

// -------- row normalization: y = x / ||x|| (256 cols, 1 block per row) --------
__global__ __launch_bounds__(256) void normalize_rows_k(const float* __restrict__ x,
                                                        float* __restrict__ y) {
    __shared__ float warpred[8];
    __shared__ float rn_s;
    const int row = blockIdx.x;
    const int t = threadIdx.x;
    float v = x[(size_t)row * C_DIM + t];
    float s = v * v;
    #pragma unroll
    for (int o = 16; o > 0; o >>= 1) s += __shfl_xor_sync(0xffffffffu, s, o);
    if ((t & 31) == 0) warpred[t >> 5] = s;
    __syncthreads();
    if (t == 0) {
        float tot = 0.f;
        #pragma unroll
        for (int i = 0; i < 8; i++) tot += warpred[i];
        rn_s = rsqrtf(tot);
    }
    __syncthreads();
    y[(size_t)row * C_DIM + t] = v * rn_s;
}

// -------- C[M,N] = A[M,256] * B[N,256]^T  (logits GEMM, K=256) --------
// 128x128 tile, BK=16, 256 threads, 8x8 per thread.
__global__ __launch_bounds__(256) void gemm_nt_k(const float* __restrict__ A,
                                                 const float* __restrict__ B,
                                                 float* __restrict__ C, int ldc) {
    __shared__ float As[16][128];
    __shared__ float Bs[16][128];
    const int tid = threadIdx.x;
    const int tx = tid & 15;
    const int ty = tid >> 4;
    const int bm = blockIdx.y;
    const int bn = blockIdx.x;
    const float* Ab = A + (size_t)bm * 128 * C_DIM;
    const float* Bb = B + (size_t)bn * 128 * C_DIM;

    float acc[8][8];
    #pragma unroll
    for (int i = 0; i < 8; i++)
        #pragma unroll
        for (int j = 0; j < 8; j++) acc[i][j] = 0.f;

    for (int k0 = 0; k0 < C_DIM; k0 += 16) {
        #pragma unroll
        for (int l = 0; l < 2; l++) {
            int q = tid + l * 256;
            int row = q >> 2;
            int c4 = (q & 3) * 4;
            float4 va = *(const float4*)(Ab + (size_t)row * C_DIM + k0 + c4);
            As[c4 + 0][row] = va.x;
            As[c4 + 1][row] = va.y;
            As[c4 + 2][row] = va.z;
            As[c4 + 3][row] = va.w;
            float4 vb = *(const float4*)(Bb + (size_t)row * C_DIM + k0 + c4);
            Bs[c4 + 0][row] = vb.x;
            Bs[c4 + 1][row] = vb.y;
            Bs[c4 + 2][row] = vb.z;
            Bs[c4 + 3][row] = vb.w;
        }
        __syncthreads();
        #pragma unroll
        for (int kk = 0; kk < 16; kk++) {
            float a[8], b[8];
            *(float4*)&a[0] = *(const float4*)&As[kk][ty * 8];
            *(float4*)&a[4] = *(const float4*)&As[kk][ty * 8 + 4];
            *(float4*)&b[0] = *(const float4*)&Bs[kk][tx * 8];
            *(float4*)&b[4] = *(const float4*)&Bs[kk][tx * 8 + 4];
            #pragma unroll
            for (int i = 0; i < 8; i++)
                #pragma unroll
                for (int j = 0; j < 8; j++) acc[i][j] = fmaf(a[i], b[j], acc[i][j]);
        }
        __syncthreads();
    }
    #pragma unroll
    for (int i = 0; i < 8; i++) {
        float* Cp = C + (size_t)(bm * 128 + ty * 8 + i) * ldc + bn * 128 + tx * 8;
        *(float4*)Cp = make_float4(acc[i][0], acc[i][1], acc[i][2], acc[i][3]);
        *(float4*)(Cp + 4) = make_float4(acc[i][4], acc[i][5], acc[i][6], acc[i][7]);
    }
}

// -------- in-place row log-softmax over 4096 cols (1 block per row) --------
__global__ __launch_bounds__(256) void softmax_rows_k(float* __restrict__ base) {
    __shared__ float warpred[8];
    __shared__ float bc;
    float* p = base + (size_t)blockIdx.x * 4096;
    const int t = threadIdx.x;
    float x[16];
    #pragma unroll
    for (int i = 0; i < 4; i++) {
        float4 v = *(const float4*)&p[i * 1024 + t * 4];
        x[i * 4 + 0] = v.x; x[i * 4 + 1] = v.y; x[i * 4 + 2] = v.z; x[i * 4 + 3] = v.w;
    }
    float mx = x[0];
    #pragma unroll
    for (int i = 1; i < 16; i++) mx = fmaxf(mx, x[i]);
    #pragma unroll
    for (int o = 16; o > 0; o >>= 1) mx = fmaxf(mx, __shfl_xor_sync(0xffffffffu, mx, o));
    if ((t & 31) == 0) warpred[t >> 5] = mx;
    __syncthreads();
    if (t == 0) {
        float m = warpred[0];
        #pragma unroll
        for (int i = 1; i < 8; i++) m = fmaxf(m, warpred[i]);
        bc = m;
    }
    __syncthreads();
    mx = bc;
    __syncthreads();
    float s = 0.f;
    #pragma unroll
    for (int i = 0; i < 16; i++) s += fexp(x[i] - mx);
    #pragma unroll
    for (int o = 16; o > 0; o >>= 1) s += __shfl_xor_sync(0xffffffffu, s, o);
    if ((t & 31) == 0) warpred[t >> 5] = s;
    __syncthreads();
    if (t == 0) {
        float tot = 0.f;
        #pragma unroll
        for (int i = 0; i < 8; i++) tot += warpred[i];
        bc = mx + logf(tot);  // lse; logf only 16384 calls total, MUFU fine
    }
    __syncthreads();
    const float lse = bc;
    #pragma unroll
    for (int i = 0; i < 4; i++) {
        float4 v = make_float4(x[i * 4 + 0] - lse, x[i * 4 + 1] - lse,
                               x[i * 4 + 2] - lse, x[i * 4 + 3] - lse);
        *(float4*)&p[i * 1024 + t * 4] = v;
    }
}

// -------- C[M,256] = exp(L[M,4096]) * V[4096,256]  (recall GEMM) --------
// 128x128 tile, BK=16, 256 threads, 8x8 per thread. L holds log_softmax.
__global__ __launch_bounds__(256) void gemm_exp_nn_k(const float* __restrict__ L,
                                                     const float* __restrict__ V,
                                                     float* __restrict__ C) {
    __shared__ float As[16][128];
    __shared__ float Bs[16][128];
    const int tid = threadIdx.x;
    const int tx = tid & 15;
    const int ty = tid >> 4;
    const int bm = blockIdx.y;
    const int bn = blockIdx.x;  // 0..1
    const float* Lb = L + (size_t)bm * 128 * S_ROWS;

    float acc[8][8];
    #pragma unroll
    for (int i = 0; i < 8; i++)
        #pragma unroll
        for (int j = 0; j < 8; j++) acc[i][j] = 0.f;

    for (int k0 = 0; k0 < S_ROWS; k0 += 16) {
        #pragma unroll
        for (int l = 0; l < 2; l++) {
            int q = tid + l * 256;
            int row = q >> 2;
            int c4 = (q & 3) * 4;
            float4 va = *(const float4*)(Lb + (size_t)row * S_ROWS + k0 + c4);
            As[c4 + 0][row] = fexp(va.x);
            As[c4 + 1][row] = fexp(va.y);
            As[c4 + 2][row] = fexp(va.z);
            As[c4 + 3][row] = fexp(va.w);
            int krow = q >> 5;
            int n4 = (q & 31) * 4;
            float4 vb = *(const float4*)(V + (size_t)(k0 + krow) * C_DIM + bn * 128 + n4);
            *(float4*)&Bs[krow][n4] = vb;
        }
        __syncthreads();
        #pragma unroll
        for (int kk = 0; kk < 16; kk++) {
            float a[8], b[8];
            *(float4*)&a[0] = *(const float4*)&As[kk][ty * 8];
            *(float4*)&a[4] = *(const float4*)&As[kk][ty * 8 + 4];
            *(float4*)&b[0] = *(const float4*)&Bs[kk][tx * 8];
            *(float4*)&b[4] = *(const float4*)&Bs[kk][tx * 8 + 4];
            #pragma unroll
            for (int i = 0; i < 8; i++)
                #pragma unroll
                for (int j = 0; j < 8; j++) acc[i][j] = fmaf(a[i], b[j], acc[i][j]);
        }
        __syncthreads();
    }
    #pragma unroll
    for (int i = 0; i < 8; i++) {
        float* Cp = C + (size_t)(bm * 128 + ty * 8 + i) * C_DIM + bn * 128 + tx * 8;
        *(float4*)Cp = make_float4(acc[i][0], acc[i][1], acc[i][2], acc[i][3]);
        *(float4*)(Cp + 4) = make_float4(acc[i][4], acc[i][5], acc[i][6], acc[i][7]);
    }
}

extern "C" void kernel_launch(void* const* d_in, const int* in_sizes, int n_in,
                              void* d_out, int out_size) {
    const float* face   = (const float*)d_in[0];
    const float* speech = (const float*)d_in[1];
    const float* svm    = (const float*)d_in[2];
    const float* fkm    = (const float*)d_in[3];
    float* out = (float*)d_out;

    float *Sn, *Fn, *Vn, *Kn;
    cudaGetSymbolAddress((void**)&Sn, g_Sn);
    cudaGetSymbolAddress((void**)&Fn, g_Fn);
    cudaGetSymbolAddress((void**)&Vn, g_Vn);
    cudaGetSymbolAddress((void**)&Kn, g_Kn);

    // Output layout (flattened tuple order, fp32 elements):
    const size_t o_se  = 0;           // speech_emb        [8192,256]
    const size_t o_ser = 2097152;     // speech_emb_recall [8192,256]
    const size_t o_fe  = 4194304;     // face_emb          [8192,256]
    const size_t o_fer = 6291456;     // face_emb_recall   [8192,256]
    const size_t o_sal = 8388608;     // speech_address_log [8192,4096]
    const size_t o_fal = 41943040;    // face_address_log   [8192,4096]

    // identity outputs
    cudaMemcpyAsync(out + o_se, speech, (size_t)N_ROWS * C_DIM * sizeof(float),
                    cudaMemcpyDeviceToDevice, 0);
    cudaMemcpyAsync(out + o_fe, face, (size_t)N_ROWS * C_DIM * sizeof(float),
                    cudaMemcpyDeviceToDevice, 0);

    // normalization
    normalize_rows_k<<<N_ROWS, 256>>>(speech, Sn);
    normalize_rows_k<<<N_ROWS, 256>>>(face, Fn);
    normalize_rows_k<<<S_ROWS, 256>>>(svm, Vn);
    normalize_rows_k<<<S_ROWS, 256>>>(fkm, Kn);

    // logits GEMMs (write raw logits into the address_log output slots)
    gemm_nt_k<<<dim3(32, 64), 256>>>(Sn, Vn, out + o_sal, S_ROWS);
    gemm_nt_k<<<dim3(32, 64), 256>>>(Fn, Kn, out + o_fal, S_ROWS);

    // in-place log-softmax over both [8192,4096] matrices (contiguous)
    softmax_rows_k<<<2 * N_ROWS, 256>>>(out + o_sal);

    // recall GEMMs: softmax = exp(log_softmax), both recalls use svm
    gemm_exp_nn_k<<<dim3(2, 64), 256>>>(out + o_sal, svm, out + o_ser);
    gemm_exp_nn_k<<<dim3(2, 64), 256>>>(out + o_fal, svm, out + o_fer);
}

// round 9
// speedup vs baseline: 2.4564x; 2.4564x over previous
#include <cuda_runtime.h>
#include <cuda_bf16.h>
#include <cstdint>

#define N_ROWS 8192
#define S_ROWS 4096
#define C_DIM  256

// ---------------- scratch (static device arrays; no runtime allocation) ----
__device__ __align__(16) __nv_bfloat16 g_Shi[N_ROWS * C_DIM], g_Slo[N_ROWS * C_DIM];
__device__ __align__(16) __nv_bfloat16 g_Fhi[N_ROWS * C_DIM], g_Flo[N_ROWS * C_DIM];
__device__ __align__(16) __nv_bfloat16 g_Vhi[S_ROWS * C_DIM], g_Vlo[S_ROWS * C_DIM];
__device__ __align__(16) __nv_bfloat16 g_Khi[S_ROWS * C_DIM], g_Klo[S_ROWS * C_DIM];
__device__ __align__(16) __nv_bfloat16 g_Vthi[C_DIM * S_ROWS], g_Vtlo[C_DIM * S_ROWS];
__device__ __align__(16) __nv_bfloat16 g_Phi[(size_t)2 * N_ROWS * S_ROWS];
__device__ __align__(16) __nv_bfloat16 g_Plo[(size_t)2 * N_ROWS * S_ROWS];

// ---------------- fast exp on FMA pipe ------------------------------------
__device__ __forceinline__ float fexp(float x) {
    x = fmaxf(x, -80.0f);
    float z = fmaf(x, 1.4426950408889634f, 12582912.0f);
    float n = z - 12582912.0f;
    float r = fmaf(n, -0.69314718055994531f, x);
    float p = 1.3888889e-3f;
    p = fmaf(p, r, 8.3333333e-3f);
    p = fmaf(p, r, 4.1666667e-2f);
    p = fmaf(p, r, 1.6666667e-1f);
    p = fmaf(p, r, 0.5f);
    p = fmaf(p, r, 1.0f);
    p = fmaf(p, r, 1.0f);
    int e = (int)n;
    return p * __int_as_float((e + 127) << 23);
}

// ---------------- normalize rows -> split bf16 hi/lo ----------------------
__global__ __launch_bounds__(256) void normalize_split_k(const float* __restrict__ x,
                                                         __nv_bfloat16* __restrict__ hi,
                                                         __nv_bfloat16* __restrict__ lo) {
    __shared__ float warpred[8];
    __shared__ float rn_s;
    const int row = blockIdx.x;
    const int t = threadIdx.x;
    float v = x[(size_t)row * C_DIM + t];
    float s = v * v;
    #pragma unroll
    for (int o = 16; o > 0; o >>= 1) s += __shfl_xor_sync(0xffffffffu, s, o);
    if ((t & 31) == 0) warpred[t >> 5] = s;
    __syncthreads();
    if (t == 0) {
        float tot = 0.f;
        #pragma unroll
        for (int i = 0; i < 8; i++) tot += warpred[i];
        rn_s = rsqrtf(tot);
    }
    __syncthreads();
    float y = v * rn_s;
    __nv_bfloat16 h = __float2bfloat16(y);
    hi[(size_t)row * C_DIM + t] = h;
    lo[(size_t)row * C_DIM + t] = __float2bfloat16(y - __bfloat162float(h));
}

// ---------------- transpose raw svm [4096,256] -> [256,4096] hi/lo --------
__global__ void transpose_split_k(const float* __restrict__ V,
                                  __nv_bfloat16* __restrict__ Thi,
                                  __nv_bfloat16* __restrict__ Tlo) {
    __shared__ float ts[32][33];
    const int tx = threadIdx.x, ty = threadIdx.y;          // 32 x 8
    const int n0 = blockIdx.x * 32, k0 = blockIdx.y * 32;
    #pragma unroll
    for (int j = 0; j < 4; j++)
        ts[ty + 8 * j][tx] = V[(size_t)(k0 + ty + 8 * j) * C_DIM + n0 + tx];
    __syncthreads();
    #pragma unroll
    for (int j = 0; j < 4; j++) {
        int n = n0 + ty + 8 * j;
        int k = k0 + tx;
        float v = ts[tx][ty + 8 * j];
        __nv_bfloat16 h = __float2bfloat16(v);
        Thi[(size_t)n * S_ROWS + k] = h;
        Tlo[(size_t)n * S_ROWS + k] = __float2bfloat16(v - __bfloat162float(h));
    }
}

// ---------------- in-place log-softmax + P=exp(logsm) hi/lo ---------------
__global__ __launch_bounds__(256) void softmax_rows_k(float* __restrict__ base,
                                                      __nv_bfloat16* __restrict__ Phi,
                                                      __nv_bfloat16* __restrict__ Plo) {
    __shared__ float warpred[8];
    __shared__ float bc;
    const size_t rbase = (size_t)blockIdx.x * 4096;
    float* p = base + rbase;
    const int t = threadIdx.x;
    float x[16];
    #pragma unroll
    for (int i = 0; i < 4; i++) {
        float4 v = *(const float4*)&p[i * 1024 + t * 4];
        x[i * 4 + 0] = v.x; x[i * 4 + 1] = v.y; x[i * 4 + 2] = v.z; x[i * 4 + 3] = v.w;
    }
    float mx = x[0];
    #pragma unroll
    for (int i = 1; i < 16; i++) mx = fmaxf(mx, x[i]);
    #pragma unroll
    for (int o = 16; o > 0; o >>= 1) mx = fmaxf(mx, __shfl_xor_sync(0xffffffffu, mx, o));
    if ((t & 31) == 0) warpred[t >> 5] = mx;
    __syncthreads();
    if (t == 0) {
        float m = warpred[0];
        #pragma unroll
        for (int i = 1; i < 8; i++) m = fmaxf(m, warpred[i]);
        bc = m;
    }
    __syncthreads();
    mx = bc;
    __syncthreads();
    float s = 0.f;
    #pragma unroll
    for (int i = 0; i < 16; i++) s += fexp(x[i] - mx);
    #pragma unroll
    for (int o = 16; o > 0; o >>= 1) s += __shfl_xor_sync(0xffffffffu, s, o);
    if ((t & 31) == 0) warpred[t >> 5] = s;
    __syncthreads();
    if (t == 0) {
        float tot = 0.f;
        #pragma unroll
        for (int i = 0; i < 8; i++) tot += warpred[i];
        bc = mx + logf(tot);
    }
    __syncthreads();
    const float lse = bc;
    #pragma unroll
    for (int i = 0; i < 4; i++) {
        float l0 = x[i * 4 + 0] - lse, l1 = x[i * 4 + 1] - lse;
        float l2 = x[i * 4 + 2] - lse, l3 = x[i * 4 + 3] - lse;
        *(float4*)&p[i * 1024 + t * 4] = make_float4(l0, l1, l2, l3);
        float p0 = fexp(l0), p1 = fexp(l1), p2 = fexp(l2), p3 = fexp(l3);
        __nv_bfloat16 h0 = __float2bfloat16(p0), h1 = __float2bfloat16(p1);
        __nv_bfloat16 h2 = __float2bfloat16(p2), h3 = __float2bfloat16(p3);
        __nv_bfloat162 a; a.x = h0; a.y = h1;
        __nv_bfloat162 b; b.x = h2; b.y = h3;
        *(__nv_bfloat162*)&Phi[rbase + i * 1024 + t * 4] = a;
        *(__nv_bfloat162*)&Phi[rbase + i * 1024 + t * 4 + 2] = b;
        __nv_bfloat162 c, d;
        c.x = __float2bfloat16(p0 - __bfloat162float(h0));
        c.y = __float2bfloat16(p1 - __bfloat162float(h1));
        d.x = __float2bfloat16(p2 - __bfloat162float(h2));
        d.y = __float2bfloat16(p3 - __bfloat162float(h3));
        *(__nv_bfloat162*)&Plo[rbase + i * 1024 + t * 4] = c;
        *(__nv_bfloat162*)&Plo[rbase + i * 1024 + t * 4 + 2] = d;
    }
}

// =================== HMMA split-bf16 GEMM ==================================
// C[M,N] = (Ahi+Alo)(Bhi+Blo)^T via 3 passes (hi*hi + hi*lo + lo*hi),
// fp32 accumulate. A:[M,K] bf16 row-major, B:[N,K] bf16 row-major.
// CTA tile 128x128, BK=32, 8 warps (warp tile 64x32), 2-stage cp.async.
// smem rows padded to 80B (5 x 16B chunks) -> conflict-free ldmatrix.

#define ROWB 80             // bytes per smem row (32 bf16 data + 8 pad)
#define TILEB (128 * ROWB)  // 10240 B per operand tile
#define STAGEB (4 * TILEB)  // Ahi,Alo,Bhi,Blo = 40960 B
// total dynamic smem = 2 * STAGEB = 81920

__device__ __forceinline__ void cp16(uint32_t d, const void* g) {
    asm volatile("cp.async.cg.shared.global [%0], [%1], 16;" :: "r"(d), "l"(g) : "memory");
}
__device__ __forceinline__ void ldsm_x4(uint32_t* r, uint32_t a) {
    asm volatile("ldmatrix.sync.aligned.m8n8.x4.shared.b16 {%0,%1,%2,%3}, [%4];"
                 : "=r"(r[0]), "=r"(r[1]), "=r"(r[2]), "=r"(r[3]) : "r"(a));
}
__device__ __forceinline__ void ldsm_x2(uint32_t* r, uint32_t a) {
    asm volatile("ldmatrix.sync.aligned.m8n8.x2.shared.b16 {%0,%1}, [%2];"
                 : "=r"(r[0]), "=r"(r[1]) : "r"(a));
}
__device__ __forceinline__ void mma_bf16(float* d, const uint32_t* a, const uint32_t* b) {
    asm volatile(
        "mma.sync.aligned.m16n8k16.row.col.f32.bf16.bf16.f32 "
        "{%0,%1,%2,%3},{%4,%5,%6,%7},{%8,%9},{%0,%1,%2,%3};"
        : "+f"(d[0]), "+f"(d[1]), "+f"(d[2]), "+f"(d[3])
        : "r"(a[0]), "r"(a[1]), "r"(a[2]), "r"(a[3]), "r"(b[0]), "r"(b[1]));
}

__global__ __launch_bounds__(256, 2) void gemm3_mma_k(
    const __nv_bfloat16* __restrict__ Ahi, const __nv_bfloat16* __restrict__ Alo,
    const __nv_bfloat16* __restrict__ Bhi, const __nv_bfloat16* __restrict__ Blo,
    float* __restrict__ C, int K, int ldc) {
    extern __shared__ char smem[];
    uint32_t sb;
    asm("{ .reg .u64 t; cvta.to.shared.u64 t, %1; cvt.u32.u64 %0, t; }" : "=r"(sb) : "l"(smem));
    const int tid = threadIdx.x;
    const int wid = tid >> 5, lane = tid & 31;
    const int bm = blockIdx.y, bn = blockIdx.x;
    const int wm = (wid >> 2) * 64;   // warp row base within CTA tile
    const int wn = (wid & 3) * 32;    // warp col base

    const __nv_bfloat16* gA0 = Ahi + (size_t)bm * 128 * K;
    const __nv_bfloat16* gA1 = Alo + (size_t)bm * 128 * K;
    const __nv_bfloat16* gB0 = Bhi + (size_t)bn * 128 * K;
    const __nv_bfloat16* gB1 = Blo + (size_t)bn * 128 * K;

    // per-thread cp.async assignment: q in [0,512): row=q>>2, 16B-chunk=q&3
    const int r0 = tid >> 2, c0 = (tid & 3);
    const int r1 = (tid + 256) >> 2, c1 = ((tid + 256) & 3);

    // ldmatrix per-lane offsets
    const uint32_t aoff = (uint32_t)(((lane & 7) + ((lane >> 3) & 1) * 8) * ROWB
                                     + (lane >> 4) * 16);
    const uint32_t boff = (uint32_t)((lane & 7) * ROWB + ((lane >> 3) & 1) * 16);

    float acc[4][4][4];
    #pragma unroll
    for (int mi = 0; mi < 4; mi++)
        #pragma unroll
        for (int ni = 0; ni < 4; ni++)
            #pragma unroll
            for (int e = 0; e < 4; e++) acc[mi][ni][e] = 0.f;

    const int nch = K >> 5;  // K/32

    // ---- stage loader ----
    #define LOAD_STAGE(s, k0)                                                   \
    {                                                                           \
        uint32_t base = sb + (s) * STAGEB;                                      \
        size_t ga = (size_t)r0 * K + (k0) + c0 * 8;                             \
        uint32_t da = base + (uint32_t)(r0 * ROWB + c0 * 16);                   \
        cp16(da,              gA0 + ga);                                        \
        cp16(da + TILEB,      gA1 + ga);                                        \
        cp16(da + 2 * TILEB,  gB0 + ga);                                        \
        cp16(da + 3 * TILEB,  gB1 + ga);                                        \
        size_t gb = (size_t)r1 * K + (k0) + c1 * 8;                             \
        uint32_t db = base + (uint32_t)(r1 * ROWB + c1 * 16);                   \
        cp16(db,              gA0 + gb);                                        \
        cp16(db + TILEB,      gA1 + gb);                                        \
        cp16(db + 2 * TILEB,  gB0 + gb);                                        \
        cp16(db + 3 * TILEB,  gB1 + gb);                                        \
        asm volatile("cp.async.commit_group;" ::: "memory");                    \
    }

    LOAD_STAGE(0, 0)
    if (nch > 1) LOAD_STAGE(1, 32)

    for (int ch = 0; ch < nch; ch++) {
        if (ch + 1 < nch) {
            asm volatile("cp.async.wait_group 1;" ::: "memory");
        } else {
            asm volatile("cp.async.wait_group 0;" ::: "memory");
        }
        __syncthreads();

        uint32_t stg = sb + (uint32_t)(ch & 1) * STAGEB;
        uint32_t sA0 = stg;
        uint32_t sA1 = stg + TILEB;
        uint32_t sB0 = stg + 2 * TILEB;
        uint32_t sB1 = stg + 3 * TILEB;

        #pragma unroll
        for (int ks = 0; ks < 2; ks++) {
            const uint32_t ko = ks * 32;  // 2 chunks of 16B per k16 step
            uint32_t af[4][4], bh[4][2], bl[4][2];
            // both B frag sets (hi and lo)
            #pragma unroll
            for (int ni = 0; ni < 4; ni++) {
                ldsm_x2(bh[ni], sB0 + (wn + ni * 8) * ROWB + ko + boff);
                ldsm_x2(bl[ni], sB1 + (wn + ni * 8) * ROWB + ko + boff);
            }
            // A-hi frags
            #pragma unroll
            for (int mi = 0; mi < 4; mi++)
                ldsm_x4(af[mi], sA0 + (wm + mi * 16) * ROWB + ko + aoff);
            // pass 0: Ahi * Bhi
            #pragma unroll
            for (int mi = 0; mi < 4; mi++)
                #pragma unroll
                for (int ni = 0; ni < 4; ni++) mma_bf16(acc[mi][ni], af[mi], bh[ni]);
            // pass 1: Ahi * Blo (reuse af)
            #pragma unroll
            for (int mi = 0; mi < 4; mi++)
                #pragma unroll
                for (int ni = 0; ni < 4; ni++) mma_bf16(acc[mi][ni], af[mi], bl[ni]);
            // A-lo frags (overwrite af)
            #pragma unroll
            for (int mi = 0; mi < 4; mi++)
                ldsm_x4(af[mi], sA1 + (wm + mi * 16) * ROWB + ko + aoff);
            // pass 2: Alo * Bhi
            #pragma unroll
            for (int mi = 0; mi < 4; mi++)
                #pragma unroll
                for (int ni = 0; ni < 4; ni++) mma_bf16(acc[mi][ni], af[mi], bh[ni]);
        }
        __syncthreads();
        if (ch + 2 < nch) LOAD_STAGE(ch & 1, (ch + 2) * 32)
    }

    // ---- epilogue: fragment layout -> global fp32 ----
    const int rr = lane >> 2;
    const int cc = (lane & 3) * 2;
    #pragma unroll
    for (int mi = 0; mi < 4; mi++) {
        int grow = bm * 128 + wm + mi * 16 + rr;
        #pragma unroll
        for (int ni = 0; ni < 4; ni++) {
            int gcol = bn * 128 + wn + ni * 8 + cc;
            *(float2*)&C[(size_t)grow * ldc + gcol] =
                make_float2(acc[mi][ni][0], acc[mi][ni][1]);
            *(float2*)&C[(size_t)(grow + 8) * ldc + gcol] =
                make_float2(acc[mi][ni][2], acc[mi][ni][3]);
        }
    }
    #undef LOAD_STAGE
}

// ---------------- launch ---------------------------------------------------
extern "C" void kernel_launch(void* const* d_in, const int* in_sizes, int n_in,
                              void* d_out, int out_size) {
    const float* face   = (const float*)d_in[0];
    const float* speech = (const float*)d_in[1];
    const float* svm    = (const float*)d_in[2];
    const float* fkm    = (const float*)d_in[3];
    float* out = (float*)d_out;

    __nv_bfloat16 *Shi, *Slo, *Fhi, *Flo, *Vhi, *Vlo, *Khi, *Klo, *Vthi, *Vtlo, *Phi, *Plo;
    cudaGetSymbolAddress((void**)&Shi, g_Shi);  cudaGetSymbolAddress((void**)&Slo, g_Slo);
    cudaGetSymbolAddress((void**)&Fhi, g_Fhi);  cudaGetSymbolAddress((void**)&Flo, g_Flo);
    cudaGetSymbolAddress((void**)&Vhi, g_Vhi);  cudaGetSymbolAddress((void**)&Vlo, g_Vlo);
    cudaGetSymbolAddress((void**)&Khi, g_Khi);  cudaGetSymbolAddress((void**)&Klo, g_Klo);
    cudaGetSymbolAddress((void**)&Vthi, g_Vthi); cudaGetSymbolAddress((void**)&Vtlo, g_Vtlo);
    cudaGetSymbolAddress((void**)&Phi, g_Phi);  cudaGetSymbolAddress((void**)&Plo, g_Plo);

    const size_t o_se  = 0;
    const size_t o_ser = 2097152;
    const size_t o_fe  = 4194304;
    const size_t o_fer = 6291456;
    const size_t o_sal = 8388608;
    const size_t o_fal = 41943040;

    cudaMemcpyAsync(out + o_se, speech, (size_t)N_ROWS * C_DIM * sizeof(float),
                    cudaMemcpyDeviceToDevice, 0);
    cudaMemcpyAsync(out + o_fe, face, (size_t)N_ROWS * C_DIM * sizeof(float),
                    cudaMemcpyDeviceToDevice, 0);

    const int SMEM = 2 * STAGEB;  // 81920
    cudaFuncSetAttribute(gemm3_mma_k, cudaFuncAttributeMaxDynamicSharedMemorySize, SMEM);

    // prep: normalized hi/lo splits + raw-svm transpose
    normalize_split_k<<<N_ROWS, 256>>>(speech, Shi, Slo);
    normalize_split_k<<<N_ROWS, 256>>>(face, Fhi, Flo);
    normalize_split_k<<<S_ROWS, 256>>>(svm, Vhi, Vlo);
    normalize_split_k<<<S_ROWS, 256>>>(fkm, Khi, Klo);
    transpose_split_k<<<dim3(C_DIM / 32, S_ROWS / 32), dim3(32, 8)>>>(svm, Vthi, Vtlo);

    // logits GEMMs: [8192,4096] = [8192,256] x [4096,256]^T
    gemm3_mma_k<<<dim3(32, 64), 256, SMEM>>>(Shi, Slo, Vhi, Vlo, out + o_sal, C_DIM, S_ROWS);
    gemm3_mma_k<<<dim3(32, 64), 256, SMEM>>>(Fhi, Flo, Khi, Klo, out + o_fal, C_DIM, S_ROWS);

    // log-softmax (in place) + P = exp(logsm) split bf16
    softmax_rows_k<<<2 * N_ROWS, 256>>>(out + o_sal, Phi, Plo);

    // recall GEMMs: [8192,256] = P[8192,4096] x Vt[256,4096]^T
    gemm3_mma_k<<<dim3(2, 64), 256, SMEM>>>(Phi, Plo, Vthi, Vtlo, out + o_ser, S_ROWS, C_DIM);
    gemm3_mma_k<<<dim3(2, 64), 256, SMEM>>>(Phi + (size_t)N_ROWS * S_ROWS,
                                            Plo + (size_t)N_ROWS * S_ROWS,
                                            Vthi, Vtlo, out + o_fer, S_ROWS, C_DIM);
}

// round 10
// speedup vs baseline: 2.6114x; 1.0631x over previous
#include <cuda_runtime.h>
#include <cuda_bf16.h>
#include <cstdint>

#define N_ROWS 8192
#define S_ROWS 4096
#define C_DIM  256

// ---------------- scratch (static device arrays; no runtime allocation) ----
__device__ __align__(16) __nv_bfloat16 g_Shi[N_ROWS * C_DIM], g_Slo[N_ROWS * C_DIM];
__device__ __align__(16) __nv_bfloat16 g_Fhi[N_ROWS * C_DIM], g_Flo[N_ROWS * C_DIM];
__device__ __align__(16) __nv_bfloat16 g_Vhi[S_ROWS * C_DIM], g_Vlo[S_ROWS * C_DIM];
__device__ __align__(16) __nv_bfloat16 g_Khi[S_ROWS * C_DIM], g_Klo[S_ROWS * C_DIM];
__device__ __align__(16) __nv_bfloat16 g_Vthi[C_DIM * S_ROWS], g_Vtlo[C_DIM * S_ROWS];
__device__ __align__(16) __nv_bfloat16 g_Phi[(size_t)2 * N_ROWS * S_ROWS];
__device__ __align__(16) __nv_bfloat16 g_Plo[(size_t)2 * N_ROWS * S_ROWS];
// split-K partials for merged recall GEMM: [2 splits][16384, 256] fp32
__device__ __align__(16) float g_part[(size_t)2 * 2 * N_ROWS * C_DIM];

// ---------------- fast exp on FMA pipe ------------------------------------
__device__ __forceinline__ float fexp(float x) {
    x = fmaxf(x, -80.0f);
    float z = fmaf(x, 1.4426950408889634f, 12582912.0f);
    float n = z - 12582912.0f;
    float r = fmaf(n, -0.69314718055994531f, x);
    float p = 1.3888889e-3f;
    p = fmaf(p, r, 8.3333333e-3f);
    p = fmaf(p, r, 4.1666667e-2f);
    p = fmaf(p, r, 1.6666667e-1f);
    p = fmaf(p, r, 0.5f);
    p = fmaf(p, r, 1.0f);
    p = fmaf(p, r, 1.0f);
    int e = (int)n;
    return p * __int_as_float((e + 127) << 23);
}

// ---------------- normalize rows -> split bf16 hi/lo ----------------------
__global__ __launch_bounds__(256) void normalize_split_k(const float* __restrict__ x,
                                                         __nv_bfloat16* __restrict__ hi,
                                                         __nv_bfloat16* __restrict__ lo) {
    __shared__ float warpred[8];
    __shared__ float rn_s;
    const int row = blockIdx.x;
    const int t = threadIdx.x;
    float v = x[(size_t)row * C_DIM + t];
    float s = v * v;
    #pragma unroll
    for (int o = 16; o > 0; o >>= 1) s += __shfl_xor_sync(0xffffffffu, s, o);
    if ((t & 31) == 0) warpred[t >> 5] = s;
    __syncthreads();
    if (t == 0) {
        float tot = 0.f;
        #pragma unroll
        for (int i = 0; i < 8; i++) tot += warpred[i];
        rn_s = rsqrtf(tot);
    }
    __syncthreads();
    float y = v * rn_s;
    __nv_bfloat16 h = __float2bfloat16(y);
    hi[(size_t)row * C_DIM + t] = h;
    lo[(size_t)row * C_DIM + t] = __float2bfloat16(y - __bfloat162float(h));
}

// ---------------- transpose raw svm [4096,256] -> [256,4096] hi/lo --------
__global__ void transpose_split_k(const float* __restrict__ V,
                                  __nv_bfloat16* __restrict__ Thi,
                                  __nv_bfloat16* __restrict__ Tlo) {
    __shared__ float ts[32][33];
    const int tx = threadIdx.x, ty = threadIdx.y;          // 32 x 8
    const int n0 = blockIdx.x * 32, k0 = blockIdx.y * 32;
    #pragma unroll
    for (int j = 0; j < 4; j++)
        ts[ty + 8 * j][tx] = V[(size_t)(k0 + ty + 8 * j) * C_DIM + n0 + tx];
    __syncthreads();
    #pragma unroll
    for (int j = 0; j < 4; j++) {
        int n = n0 + ty + 8 * j;
        int k = k0 + tx;
        float v = ts[tx][ty + 8 * j];
        __nv_bfloat16 h = __float2bfloat16(v);
        Thi[(size_t)n * S_ROWS + k] = h;
        Tlo[(size_t)n * S_ROWS + k] = __float2bfloat16(v - __bfloat162float(h));
    }
}

// ---------------- in-place log-softmax + P=exp(logsm) hi/lo ---------------
__global__ __launch_bounds__(256) void softmax_rows_k(float* __restrict__ base,
                                                      __nv_bfloat16* __restrict__ Phi,
                                                      __nv_bfloat16* __restrict__ Plo) {
    __shared__ float warpred[8];
    __shared__ float bc;
    const size_t rbase = (size_t)blockIdx.x * 4096;
    float* p = base + rbase;
    const int t = threadIdx.x;
    float x[16];
    #pragma unroll
    for (int i = 0; i < 4; i++) {
        float4 v = *(const float4*)&p[i * 1024 + t * 4];
        x[i * 4 + 0] = v.x; x[i * 4 + 1] = v.y; x[i * 4 + 2] = v.z; x[i * 4 + 3] = v.w;
    }
    float mx = x[0];
    #pragma unroll
    for (int i = 1; i < 16; i++) mx = fmaxf(mx, x[i]);
    #pragma unroll
    for (int o = 16; o > 0; o >>= 1) mx = fmaxf(mx, __shfl_xor_sync(0xffffffffu, mx, o));
    if ((t & 31) == 0) warpred[t >> 5] = mx;
    __syncthreads();
    if (t == 0) {
        float m = warpred[0];
        #pragma unroll
        for (int i = 1; i < 8; i++) m = fmaxf(m, warpred[i]);
        bc = m;
    }
    __syncthreads();
    mx = bc;
    __syncthreads();
    float s = 0.f;
    #pragma unroll
    for (int i = 0; i < 16; i++) s += fexp(x[i] - mx);
    #pragma unroll
    for (int o = 16; o > 0; o >>= 1) s += __shfl_xor_sync(0xffffffffu, s, o);
    if ((t & 31) == 0) warpred[t >> 5] = s;
    __syncthreads();
    if (t == 0) {
        float tot = 0.f;
        #pragma unroll
        for (int i = 0; i < 8; i++) tot += warpred[i];
        bc = mx + logf(tot);
    }
    __syncthreads();
    const float lse = bc;
    #pragma unroll
    for (int i = 0; i < 4; i++) {
        float l0 = x[i * 4 + 0] - lse, l1 = x[i * 4 + 1] - lse;
        float l2 = x[i * 4 + 2] - lse, l3 = x[i * 4 + 3] - lse;
        *(float4*)&p[i * 1024 + t * 4] = make_float4(l0, l1, l2, l3);
        float p0 = fexp(l0), p1 = fexp(l1), p2 = fexp(l2), p3 = fexp(l3);
        __nv_bfloat16 h0 = __float2bfloat16(p0), h1 = __float2bfloat16(p1);
        __nv_bfloat16 h2 = __float2bfloat16(p2), h3 = __float2bfloat16(p3);
        __nv_bfloat162 a; a.x = h0; a.y = h1;
        __nv_bfloat162 b; b.x = h2; b.y = h3;
        *(__nv_bfloat162*)&Phi[rbase + i * 1024 + t * 4] = a;
        *(__nv_bfloat162*)&Phi[rbase + i * 1024 + t * 4 + 2] = b;
        __nv_bfloat162 c, d;
        c.x = __float2bfloat16(p0 - __bfloat162float(h0));
        c.y = __float2bfloat16(p1 - __bfloat162float(h1));
        d.x = __float2bfloat16(p2 - __bfloat162float(h2));
        d.y = __float2bfloat16(p3 - __bfloat162float(h3));
        *(__nv_bfloat162*)&Plo[rbase + i * 1024 + t * 4] = c;
        *(__nv_bfloat162*)&Plo[rbase + i * 1024 + t * 4 + 2] = d;
    }
}

// =================== HMMA split-bf16 GEMM body =============================
// C[M,N] += over k-range: (Ahi+Alo)(Bhi+Blo)^T via 3 passes
// (hi*hi + hi*lo + lo*hi), fp32 accumulate.
// A:[M,K] bf16 row-major, B:[N,K] bf16 row-major.
// CTA tile 128x128, BK=32, 8 warps (warp tile 64x32), 2-stage cp.async.
// smem rows padded to 80B (5 x 16B chunks) -> conflict-free ldmatrix.

#define ROWB 80             // bytes per smem row (32 bf16 data + 8 pad)
#define TILEB (128 * ROWB)  // 10240 B per operand tile
#define STAGEB (4 * TILEB)  // Ahi,Alo,Bhi,Blo = 40960 B
#define GEMM_SMEM (2 * STAGEB)  // 81920

__device__ __forceinline__ void cp16(uint32_t d, const void* g) {
    asm volatile("cp.async.cg.shared.global [%0], [%1], 16;" :: "r"(d), "l"(g) : "memory");
}
__device__ __forceinline__ void ldsm_x4(uint32_t* r, uint32_t a) {
    asm volatile("ldmatrix.sync.aligned.m8n8.x4.shared.b16 {%0,%1,%2,%3}, [%4];"
                 : "=r"(r[0]), "=r"(r[1]), "=r"(r[2]), "=r"(r[3]) : "r"(a));
}
__device__ __forceinline__ void ldsm_x2(uint32_t* r, uint32_t a) {
    asm volatile("ldmatrix.sync.aligned.m8n8.x2.shared.b16 {%0,%1}, [%2];"
                 : "=r"(r[0]), "=r"(r[1]) : "r"(a));
}
__device__ __forceinline__ void mma_bf16(float* d, const uint32_t* a, const uint32_t* b) {
    asm volatile(
        "mma.sync.aligned.m16n8k16.row.col.f32.bf16.bf16.f32 "
        "{%0,%1,%2,%3},{%4,%5,%6,%7},{%8,%9},{%0,%1,%2,%3};"
        : "+f"(d[0]), "+f"(d[1]), "+f"(d[2]), "+f"(d[3])
        : "r"(a[0]), "r"(a[1]), "r"(a[2]), "r"(a[3]), "r"(b[0]), "r"(b[1]));
}

__device__ __forceinline__ void gemm3_body(
    const __nv_bfloat16* __restrict__ Ahi, const __nv_bfloat16* __restrict__ Alo,
    const __nv_bfloat16* __restrict__ Bhi, const __nv_bfloat16* __restrict__ Blo,
    float* __restrict__ C, int K, int ldc, int ch0, int nch, int bm, int bn) {
    extern __shared__ char smem[];
    uint32_t sb;
    asm("{ .reg .u64 t; cvta.to.shared.u64 t, %1; cvt.u32.u64 %0, t; }" : "=r"(sb) : "l"(smem));
    const int tid = threadIdx.x;
    const int wid = tid >> 5, lane = tid & 31;
    const int wm = (wid >> 2) * 64;   // warp row base within CTA tile
    const int wn = (wid & 3) * 32;    // warp col base

    const __nv_bfloat16* gA0 = Ahi + (size_t)bm * 128 * K;
    const __nv_bfloat16* gA1 = Alo + (size_t)bm * 128 * K;
    const __nv_bfloat16* gB0 = Bhi + (size_t)bn * 128 * K;
    const __nv_bfloat16* gB1 = Blo + (size_t)bn * 128 * K;

    // per-thread cp.async assignment: q in [0,512): row=q>>2, 16B-chunk=q&3
    const int r0 = tid >> 2, c0 = (tid & 3);
    const int r1 = (tid + 256) >> 2, c1 = ((tid + 256) & 3);

    // ldmatrix per-lane offsets
    const uint32_t aoff = (uint32_t)(((lane & 7) + ((lane >> 3) & 1) * 8) * ROWB
                                     + (lane >> 4) * 16);
    const uint32_t boff = (uint32_t)((lane & 7) * ROWB + ((lane >> 3) & 1) * 16);

    float acc[4][4][4];
    #pragma unroll
    for (int mi = 0; mi < 4; mi++)
        #pragma unroll
        for (int ni = 0; ni < 4; ni++)
            #pragma unroll
            for (int e = 0; e < 4; e++) acc[mi][ni][e] = 0.f;

    // ---- stage loader ----
    #define LOAD_STAGE(s, k0)                                                   \
    {                                                                           \
        uint32_t base = sb + (s) * STAGEB;                                      \
        size_t ga = (size_t)r0 * K + (k0) + c0 * 8;                             \
        uint32_t da = base + (uint32_t)(r0 * ROWB + c0 * 16);                   \
        cp16(da,              gA0 + ga);                                        \
        cp16(da + TILEB,      gA1 + ga);                                        \
        cp16(da + 2 * TILEB,  gB0 + ga);                                        \
        cp16(da + 3 * TILEB,  gB1 + ga);                                        \
        size_t gb = (size_t)r1 * K + (k0) + c1 * 8;                             \
        uint32_t db = base + (uint32_t)(r1 * ROWB + c1 * 16);                   \
        cp16(db,              gA0 + gb);                                        \
        cp16(db + TILEB,      gA1 + gb);                                        \
        cp16(db + 2 * TILEB,  gB0 + gb);                                        \
        cp16(db + 3 * TILEB,  gB1 + gb);                                        \
        asm volatile("cp.async.commit_group;" ::: "memory");                    \
    }

    LOAD_STAGE(0, ch0 * 32)
    if (nch > 1) LOAD_STAGE(1, (ch0 + 1) * 32)

    for (int ch = 0; ch < nch; ch++) {
        if (ch + 1 < nch) {
            asm volatile("cp.async.wait_group 1;" ::: "memory");
        } else {
            asm volatile("cp.async.wait_group 0;" ::: "memory");
        }
        __syncthreads();

        uint32_t stg = sb + (uint32_t)(ch & 1) * STAGEB;
        uint32_t sA0 = stg;
        uint32_t sA1 = stg + TILEB;
        uint32_t sB0 = stg + 2 * TILEB;
        uint32_t sB1 = stg + 3 * TILEB;

        #pragma unroll
        for (int ks = 0; ks < 2; ks++) {
            const uint32_t ko = ks * 32;  // 2 chunks of 16B per k16 step
            uint32_t af[4][4], bh[4][2], bl[4][2];
            // both B frag sets (hi and lo)
            #pragma unroll
            for (int ni = 0; ni < 4; ni++) {
                ldsm_x2(bh[ni], sB0 + (wn + ni * 8) * ROWB + ko + boff);
                ldsm_x2(bl[ni], sB1 + (wn + ni * 8) * ROWB + ko + boff);
            }
            // A-hi frags
            #pragma unroll
            for (int mi = 0; mi < 4; mi++)
                ldsm_x4(af[mi], sA0 + (wm + mi * 16) * ROWB + ko + aoff);
            // pass 0: Ahi * Bhi
            #pragma unroll
            for (int mi = 0; mi < 4; mi++)
                #pragma unroll
                for (int ni = 0; ni < 4; ni++) mma_bf16(acc[mi][ni], af[mi], bh[ni]);
            // pass 1: Ahi * Blo (reuse af)
            #pragma unroll
            for (int mi = 0; mi < 4; mi++)
                #pragma unroll
                for (int ni = 0; ni < 4; ni++) mma_bf16(acc[mi][ni], af[mi], bl[ni]);
            // A-lo frags (overwrite af)
            #pragma unroll
            for (int mi = 0; mi < 4; mi++)
                ldsm_x4(af[mi], sA1 + (wm + mi * 16) * ROWB + ko + aoff);
            // pass 2: Alo * Bhi
            #pragma unroll
            for (int mi = 0; mi < 4; mi++)
                #pragma unroll
                for (int ni = 0; ni < 4; ni++) mma_bf16(acc[mi][ni], af[mi], bh[ni]);
        }
        __syncthreads();
        if (ch + 2 < nch) LOAD_STAGE(ch & 1, (ch0 + ch + 2) * 32)
    }

    // ---- epilogue: fragment layout -> global fp32 ----
    const int rr = lane >> 2;
    const int cc = (lane & 3) * 2;
    #pragma unroll
    for (int mi = 0; mi < 4; mi++) {
        int grow = bm * 128 + wm + mi * 16 + rr;
        #pragma unroll
        for (int ni = 0; ni < 4; ni++) {
            int gcol = bn * 128 + wn + ni * 8 + cc;
            *(float2*)&C[(size_t)grow * ldc + gcol] =
                make_float2(acc[mi][ni][0], acc[mi][ni][1]);
            *(float2*)&C[(size_t)(grow + 8) * ldc + gcol] =
                make_float2(acc[mi][ni][2], acc[mi][ni][3]);
        }
    }
    #undef LOAD_STAGE
}

// ---- merged logits GEMM: z=0 -> speech/svm, z=1 -> face/fkm --------------
__global__ __launch_bounds__(256, 2) void gemm_logits_k(
    const __nv_bfloat16* __restrict__ Shi, const __nv_bfloat16* __restrict__ Slo,
    const __nv_bfloat16* __restrict__ Vhi, const __nv_bfloat16* __restrict__ Vlo,
    const __nv_bfloat16* __restrict__ Fhi, const __nv_bfloat16* __restrict__ Flo,
    const __nv_bfloat16* __restrict__ Khi, const __nv_bfloat16* __restrict__ Klo,
    float* __restrict__ C) {
    const int z = blockIdx.z;
    const __nv_bfloat16* A0 = z ? Fhi : Shi;
    const __nv_bfloat16* A1 = z ? Flo : Slo;
    const __nv_bfloat16* B0 = z ? Khi : Vhi;
    const __nv_bfloat16* B1 = z ? Klo : Vlo;
    float* Cz = C + (size_t)z * N_ROWS * S_ROWS;
    gemm3_body(A0, A1, B0, B1, Cz, C_DIM, S_ROWS, 0, C_DIM / 32,
               blockIdx.y, blockIdx.x);
}

// ---- merged recall GEMM with split-K=2: M=16384, partials to g_part ------
__global__ __launch_bounds__(256, 2) void gemm_recall_k(
    const __nv_bfloat16* __restrict__ Phi, const __nv_bfloat16* __restrict__ Plo,
    const __nv_bfloat16* __restrict__ Vthi, const __nv_bfloat16* __restrict__ Vtlo,
    float* __restrict__ part) {
    const int z = blockIdx.z;                       // K half
    float* Cz = part + (size_t)z * 2 * N_ROWS * C_DIM;
    gemm3_body(Phi, Plo, Vthi, Vtlo, Cz, S_ROWS, C_DIM,
               z * 64, 64, blockIdx.y, blockIdx.x);
}

// ---- reduce split-K partials and scatter to the two recall outputs -------
__global__ __launch_bounds__(256) void reduce_recall_k(const float* __restrict__ part,
                                                       float* __restrict__ outS,
                                                       float* __restrict__ outF) {
    const size_t i = ((size_t)blockIdx.x * 256 + threadIdx.x) * 4;  // over 16384*256 floats
    float4 a = *(const float4*)&part[i];
    float4 b = *(const float4*)&part[i + (size_t)2 * N_ROWS * C_DIM];
    a.x += b.x; a.y += b.y; a.z += b.z; a.w += b.w;
    const size_t half = (size_t)N_ROWS * C_DIM;
    if (i < half) *(float4*)&outS[i] = a;
    else          *(float4*)&outF[i - half] = a;
}

// ---------------- launch ---------------------------------------------------
extern "C" void kernel_launch(void* const* d_in, const int* in_sizes, int n_in,
                              void* d_out, int out_size) {
    const float* face   = (const float*)d_in[0];
    const float* speech = (const float*)d_in[1];
    const float* svm    = (const float*)d_in[2];
    const float* fkm    = (const float*)d_in[3];
    float* out = (float*)d_out;

    __nv_bfloat16 *Shi, *Slo, *Fhi, *Flo, *Vhi, *Vlo, *Khi, *Klo, *Vthi, *Vtlo, *Phi, *Plo;
    float* Part;
    cudaGetSymbolAddress((void**)&Shi, g_Shi);  cudaGetSymbolAddress((void**)&Slo, g_Slo);
    cudaGetSymbolAddress((void**)&Fhi, g_Fhi);  cudaGetSymbolAddress((void**)&Flo, g_Flo);
    cudaGetSymbolAddress((void**)&Vhi, g_Vhi);  cudaGetSymbolAddress((void**)&Vlo, g_Vlo);
    cudaGetSymbolAddress((void**)&Khi, g_Khi);  cudaGetSymbolAddress((void**)&Klo, g_Klo);
    cudaGetSymbolAddress((void**)&Vthi, g_Vthi); cudaGetSymbolAddress((void**)&Vtlo, g_Vtlo);
    cudaGetSymbolAddress((void**)&Phi, g_Phi);  cudaGetSymbolAddress((void**)&Plo, g_Plo);
    cudaGetSymbolAddress((void**)&Part, g_part);

    const size_t o_se  = 0;
    const size_t o_ser = 2097152;
    const size_t o_fe  = 4194304;
    const size_t o_fer = 6291456;
    const size_t o_sal = 8388608;

    cudaMemcpyAsync(out + o_se, speech, (size_t)N_ROWS * C_DIM * sizeof(float),
                    cudaMemcpyDeviceToDevice, 0);
    cudaMemcpyAsync(out + o_fe, face, (size_t)N_ROWS * C_DIM * sizeof(float),
                    cudaMemcpyDeviceToDevice, 0);

    cudaFuncSetAttribute(gemm_logits_k, cudaFuncAttributeMaxDynamicSharedMemorySize, GEMM_SMEM);
    cudaFuncSetAttribute(gemm_recall_k, cudaFuncAttributeMaxDynamicSharedMemorySize, GEMM_SMEM);

    // prep: normalized hi/lo splits + raw-svm transpose
    normalize_split_k<<<N_ROWS, 256>>>(speech, Shi, Slo);
    normalize_split_k<<<N_ROWS, 256>>>(face, Fhi, Flo);
    normalize_split_k<<<S_ROWS, 256>>>(svm, Vhi, Vlo);
    normalize_split_k<<<S_ROWS, 256>>>(fkm, Khi, Klo);
    transpose_split_k<<<dim3(C_DIM / 32, S_ROWS / 32), dim3(32, 8)>>>(svm, Vthi, Vtlo);

    // merged logits GEMM: [2][8192,4096] = A[8192,256] x B[4096,256]^T
    gemm_logits_k<<<dim3(32, 64, 2), 256, GEMM_SMEM>>>(Shi, Slo, Vhi, Vlo,
                                                       Fhi, Flo, Khi, Klo, out + o_sal);

    // log-softmax (in place) + P = exp(logsm) split bf16 over both matrices
    softmax_rows_k<<<2 * N_ROWS, 256>>>(out + o_sal, Phi, Plo);

    // merged recall GEMM (M=16384) with split-K=2 -> partials, then reduce
    gemm_recall_k<<<dim3(2, 128, 2), 256, GEMM_SMEM>>>(Phi, Plo, Vthi, Vtlo, Part);
    reduce_recall_k<<<(2 * N_ROWS * C_DIM) / (256 * 4), 256>>>(Part, out + o_ser, out + o_fer);
}

// round 12
// speedup vs baseline: 2.6217x; 1.0039x over previous
#include <cuda_runtime.h>
#include <cuda_bf16.h>
#include <cstdint>

#define N_ROWS 8192
#define S_ROWS 4096
#define C_DIM  256

// ---------------- scratch (static device arrays; no runtime allocation) ----
__device__ __align__(16) __nv_bfloat16 g_Shi[N_ROWS * C_DIM], g_Slo[N_ROWS * C_DIM];
__device__ __align__(16) __nv_bfloat16 g_Fhi[N_ROWS * C_DIM], g_Flo[N_ROWS * C_DIM];
__device__ __align__(16) __nv_bfloat16 g_Vhi[S_ROWS * C_DIM], g_Vlo[S_ROWS * C_DIM];
__device__ __align__(16) __nv_bfloat16 g_Khi[S_ROWS * C_DIM], g_Klo[S_ROWS * C_DIM];
__device__ __align__(16) __nv_bfloat16 g_Vthi[C_DIM * S_ROWS], g_Vtlo[C_DIM * S_ROWS];
__device__ __align__(16) __nv_bfloat16 g_Phi[(size_t)2 * N_ROWS * S_ROWS];
__device__ __align__(16) __nv_bfloat16 g_Plo[(size_t)2 * N_ROWS * S_ROWS];
// split-K partials for merged recall GEMM: [2 splits][16384, 256] fp32
__device__ __align__(16) float g_part[(size_t)2 * 2 * N_ROWS * C_DIM];

// ---------------- fast exp on FMA pipe ------------------------------------
__device__ __forceinline__ float fexp(float x) {
    x = fmaxf(x, -80.0f);
    float z = fmaf(x, 1.4426950408889634f, 12582912.0f);
    float n = z - 12582912.0f;
    float r = fmaf(n, -0.69314718055994531f, x);
    float p = 1.3888889e-3f;
    p = fmaf(p, r, 8.3333333e-3f);
    p = fmaf(p, r, 4.1666667e-2f);
    p = fmaf(p, r, 1.6666667e-1f);
    p = fmaf(p, r, 0.5f);
    p = fmaf(p, r, 1.0f);
    p = fmaf(p, r, 1.0f);
    int e = (int)n;
    return p * __int_as_float((e + 127) << 23);
}

// ---------------- row normalize + hi/lo split core ------------------------
__device__ __forceinline__ void norm_row(const float* __restrict__ x,
                                         __nv_bfloat16* __restrict__ hi,
                                         __nv_bfloat16* __restrict__ lo,
                                         int row, int t) {
    __shared__ float warpred[8];
    __shared__ float rn_s;
    float v = x[(size_t)row * C_DIM + t];
    float s = v * v;
    #pragma unroll
    for (int o = 16; o > 0; o >>= 1) s += __shfl_xor_sync(0xffffffffu, s, o);
    if ((t & 31) == 0) warpred[t >> 5] = s;
    __syncthreads();
    if (t == 0) {
        float tot = 0.f;
        #pragma unroll
        for (int i = 0; i < 8; i++) tot += warpred[i];
        rn_s = rsqrtf(tot);
    }
    __syncthreads();
    float y = v * rn_s;
    __nv_bfloat16 h = __float2bfloat16(y);
    hi[(size_t)row * C_DIM + t] = h;
    lo[(size_t)row * C_DIM + t] = __float2bfloat16(y - __bfloat162float(h));
}

// merged embedding normalize: rows [0,8192) speech, [8192,16384) face
__global__ __launch_bounds__(256) void norm_emb_k(const float* __restrict__ speech,
                                                  const float* __restrict__ face,
                                                  __nv_bfloat16* __restrict__ Shi,
                                                  __nv_bfloat16* __restrict__ Slo,
                                                  __nv_bfloat16* __restrict__ Fhi,
                                                  __nv_bfloat16* __restrict__ Flo) {
    const int b = blockIdx.x;
    if (b < N_ROWS) norm_row(speech, Shi, Slo, b, threadIdx.x);
    else            norm_row(face, Fhi, Flo, b - N_ROWS, threadIdx.x);
}

// merged memory normalize: rows [0,4096) svm, [4096,8192) fkm
__global__ __launch_bounds__(256) void norm_mem_k(const float* __restrict__ svm,
                                                  const float* __restrict__ fkm,
                                                  __nv_bfloat16* __restrict__ Vhi,
                                                  __nv_bfloat16* __restrict__ Vlo,
                                                  __nv_bfloat16* __restrict__ Khi,
                                                  __nv_bfloat16* __restrict__ Klo) {
    const int b = blockIdx.x;
    if (b < S_ROWS) norm_row(svm, Vhi, Vlo, b, threadIdx.x);
    else            norm_row(fkm, Khi, Klo, b - S_ROWS, threadIdx.x);
}

// ---------------- transpose raw svm [4096,256] -> [256,4096] hi/lo --------
__global__ void transpose_split_k(const float* __restrict__ V,
                                  __nv_bfloat16* __restrict__ Thi,
                                  __nv_bfloat16* __restrict__ Tlo) {
    __shared__ float ts[32][33];
    const int tx = threadIdx.x, ty = threadIdx.y;          // 32 x 8
    const int n0 = blockIdx.x * 32, k0 = blockIdx.y * 32;
    #pragma unroll
    for (int j = 0; j < 4; j++)
        ts[ty + 8 * j][tx] = V[(size_t)(k0 + ty + 8 * j) * C_DIM + n0 + tx];
    __syncthreads();
    #pragma unroll
    for (int j = 0; j < 4; j++) {
        int n = n0 + ty + 8 * j;
        int k = k0 + tx;
        float v = ts[tx][ty + 8 * j];
        __nv_bfloat16 h = __float2bfloat16(v);
        Thi[(size_t)n * S_ROWS + k] = h;
        Tlo[(size_t)n * S_ROWS + k] = __float2bfloat16(v - __bfloat162float(h));
    }
}

// ---------------- in-place log-softmax + P=exp(logsm) hi/lo ---------------
__global__ __launch_bounds__(256) void softmax_rows_k(float* __restrict__ base,
                                                      __nv_bfloat16* __restrict__ Phi,
                                                      __nv_bfloat16* __restrict__ Plo) {
    __shared__ float warpred[8];
    __shared__ float bc;
    const size_t rbase = (size_t)blockIdx.x * 4096;
    float* p = base + rbase;
    const int t = threadIdx.x;
    float x[16];
    #pragma unroll
    for (int i = 0; i < 4; i++) {
        float4 v = *(const float4*)&p[i * 1024 + t * 4];
        x[i * 4 + 0] = v.x; x[i * 4 + 1] = v.y; x[i * 4 + 2] = v.z; x[i * 4 + 3] = v.w;
    }
    float mx = x[0];
    #pragma unroll
    for (int i = 1; i < 16; i++) mx = fmaxf(mx, x[i]);
    #pragma unroll
    for (int o = 16; o > 0; o >>= 1) mx = fmaxf(mx, __shfl_xor_sync(0xffffffffu, mx, o));
    if ((t & 31) == 0) warpred[t >> 5] = mx;
    __syncthreads();
    if (t == 0) {
        float m = warpred[0];
        #pragma unroll
        for (int i = 1; i < 8; i++) m = fmaxf(m, warpred[i]);
        bc = m;
    }
    __syncthreads();
    mx = bc;
    __syncthreads();
    float s = 0.f;
    #pragma unroll
    for (int i = 0; i < 16; i++) s += fexp(x[i] - mx);
    #pragma unroll
    for (int o = 16; o > 0; o >>= 1) s += __shfl_xor_sync(0xffffffffu, s, o);
    if ((t & 31) == 0) warpred[t >> 5] = s;
    __syncthreads();
    if (t == 0) {
        float tot = 0.f;
        #pragma unroll
        for (int i = 0; i < 8; i++) tot += warpred[i];
        bc = mx + logf(tot);
    }
    __syncthreads();
    const float lse = bc;
    #pragma unroll
    for (int i = 0; i < 4; i++) {
        float l0 = x[i * 4 + 0] - lse, l1 = x[i * 4 + 1] - lse;
        float l2 = x[i * 4 + 2] - lse, l3 = x[i * 4 + 3] - lse;
        *(float4*)&p[i * 1024 + t * 4] = make_float4(l0, l1, l2, l3);
        float p0 = fexp(l0), p1 = fexp(l1), p2 = fexp(l2), p3 = fexp(l3);
        __nv_bfloat16 h0 = __float2bfloat16(p0), h1 = __float2bfloat16(p1);
        __nv_bfloat16 h2 = __float2bfloat16(p2), h3 = __float2bfloat16(p3);
        __nv_bfloat162 a; a.x = h0; a.y = h1;
        __nv_bfloat162 b; b.x = h2; b.y = h3;
        *(__nv_bfloat162*)&Phi[rbase + i * 1024 + t * 4] = a;
        *(__nv_bfloat162*)&Phi[rbase + i * 1024 + t * 4 + 2] = b;
        __nv_bfloat162 c, d;
        c.x = __float2bfloat16(p0 - __bfloat162float(h0));
        c.y = __float2bfloat16(p1 - __bfloat162float(h1));
        d.x = __float2bfloat16(p2 - __bfloat162float(h2));
        d.y = __float2bfloat16(p3 - __bfloat162float(h3));
        *(__nv_bfloat162*)&Plo[rbase + i * 1024 + t * 4] = c;
        *(__nv_bfloat162*)&Plo[rbase + i * 1024 + t * 4 + 2] = d;
    }
}

// =================== HMMA split-bf16 GEMM body =============================
// C[M,N] += over k-range: (Ahi+Alo)(Bhi+Blo)^T via 3 passes
// (hi*hi + hi*lo + lo*hi), fp32 accumulate.
// A:[M,K] bf16 row-major, B:[N,K] bf16 row-major.
// CTA tile 128x128, BK=32, 8 warps (warp tile 64x32), 2-stage cp.async.
// smem rows padded to 80B (5 x 16B chunks) -> conflict-free ldmatrix.

#define ROWB 80             // bytes per smem row (32 bf16 data + 8 pad)
#define TILEB (128 * ROWB)  // 10240 B per operand tile
#define STAGEB (4 * TILEB)  // Ahi,Alo,Bhi,Blo = 40960 B
#define GEMM_SMEM (2 * STAGEB)  // 81920

__device__ __forceinline__ void cp16(uint32_t d, const void* g) {
    asm volatile("cp.async.cg.shared.global [%0], [%1], 16;" :: "r"(d), "l"(g) : "memory");
}
__device__ __forceinline__ void ldsm_x4(uint32_t* r, uint32_t a) {
    asm volatile("ldmatrix.sync.aligned.m8n8.x4.shared.b16 {%0,%1,%2,%3}, [%4];"
                 : "=r"(r[0]), "=r"(r[1]), "=r"(r[2]), "=r"(r[3]) : "r"(a));
}
__device__ __forceinline__ void mma_bf16(float* d, const uint32_t* a, const uint32_t* b) {
    asm volatile(
        "mma.sync.aligned.m16n8k16.row.col.f32.bf16.bf16.f32 "
        "{%0,%1,%2,%3},{%4,%5,%6,%7},{%8,%9},{%0,%1,%2,%3};"
        : "+f"(d[0]), "+f"(d[1]), "+f"(d[2]), "+f"(d[3])
        : "r"(a[0]), "r"(a[1]), "r"(a[2]), "r"(a[3]), "r"(b[0]), "r"(b[1]));
}

__device__ __forceinline__ void gemm3_body(
    const __nv_bfloat16* __restrict__ Ahi, const __nv_bfloat16* __restrict__ Alo,
    const __nv_bfloat16* __restrict__ Bhi, const __nv_bfloat16* __restrict__ Blo,
    float* __restrict__ C, int K, int ldc, int ch0, int nch, int bm, int bn) {
    extern __shared__ char smem[];
    uint32_t sb;
    asm("{ .reg .u64 t; cvta.to.shared.u64 t, %1; cvt.u32.u64 %0, t; }" : "=r"(sb) : "l"(smem));
    const int tid = threadIdx.x;
    const int wid = tid >> 5, lane = tid & 31;
    const int wm = (wid >> 2) * 64;   // warp row base within CTA tile
    const int wn = (wid & 3) * 32;    // warp col base

    const __nv_bfloat16* gA0 = Ahi + (size_t)bm * 128 * K;
    const __nv_bfloat16* gA1 = Alo + (size_t)bm * 128 * K;
    const __nv_bfloat16* gB0 = Bhi + (size_t)bn * 128 * K;
    const __nv_bfloat16* gB1 = Blo + (size_t)bn * 128 * K;

    // per-thread cp.async assignment: q in [0,512): row=q>>2, 16B-chunk=q&3
    const int r0 = tid >> 2, c0 = (tid & 3);
    const int r1 = (tid + 256) >> 2, c1 = ((tid + 256) & 3);

    // ldmatrix per-lane offsets
    // A x4: lanes 0-7 mat0 rows, 8-15 mat1 rows (+8), 16-31 k+16B halves
    const uint32_t aoff = (uint32_t)(((lane & 7) + ((lane >> 3) & 1) * 8) * ROWB
                                     + (lane >> 4) * 16);
    // B x4 (two n8 groups per instr): lanes 0-7 mat0 (n rows, k0), 8-15 mat1 (k+16B),
    // 16-23 mat2 (n rows +8, k0), 24-31 mat3 (n+8, k+16B)
    const uint32_t boff4 = (uint32_t)(((lane >> 4) * 8 + (lane & 7)) * ROWB
                                      + ((lane >> 3) & 1) * 16);

    float acc[4][4][4];
    #pragma unroll
    for (int mi = 0; mi < 4; mi++)
        #pragma unroll
        for (int ni = 0; ni < 4; ni++)
            #pragma unroll
            for (int e = 0; e < 4; e++) acc[mi][ni][e] = 0.f;

    // ---- stage loader ----
    #define LOAD_STAGE(s, k0)                                                   \
    {                                                                           \
        uint32_t base = sb + (s) * STAGEB;                                      \
        size_t ga = (size_t)r0 * K + (k0) + c0 * 8;                             \
        uint32_t da = base + (uint32_t)(r0 * ROWB + c0 * 16);                   \
        cp16(da,              gA0 + ga);                                        \
        cp16(da + TILEB,      gA1 + ga);                                        \
        cp16(da + 2 * TILEB,  gB0 + ga);                                        \
        cp16(da + 3 * TILEB,  gB1 + ga);                                        \
        size_t gb = (size_t)r1 * K + (k0) + c1 * 8;                             \
        uint32_t db = base + (uint32_t)(r1 * ROWB + c1 * 16);                   \
        cp16(db,              gA0 + gb);                                        \
        cp16(db + TILEB,      gA1 + gb);                                        \
        cp16(db + 2 * TILEB,  gB0 + gb);                                        \
        cp16(db + 3 * TILEB,  gB1 + gb);                                        \
        asm volatile("cp.async.commit_group;" ::: "memory");                    \
    }

    LOAD_STAGE(0, ch0 * 32)
    if (nch > 1) LOAD_STAGE(1, (ch0 + 1) * 32)

    for (int ch = 0; ch < nch; ch++) {
        if (ch + 1 < nch) {
            asm volatile("cp.async.wait_group 1;" ::: "memory");
        } else {
            asm volatile("cp.async.wait_group 0;" ::: "memory");
        }
        __syncthreads();

        uint32_t stg = sb + (uint32_t)(ch & 1) * STAGEB;
        uint32_t sA0 = stg;
        uint32_t sA1 = stg + TILEB;
        uint32_t sB0 = stg + 2 * TILEB;
        uint32_t sB1 = stg + 3 * TILEB;

        #pragma unroll
        for (int ks = 0; ks < 2; ks++) {
            const uint32_t ko = ks * 32;  // 2 chunks of 16B per k16 step
            uint32_t af[4][4], bh[2][4], bl[2][4];
            // B frags: each x4 covers two n8 groups (hi and lo sets)
            #pragma unroll
            for (int g = 0; g < 2; g++) {
                ldsm_x4(bh[g], sB0 + (wn + g * 16) * ROWB + ko + boff4);
                ldsm_x4(bl[g], sB1 + (wn + g * 16) * ROWB + ko + boff4);
            }
            // A-hi frags
            #pragma unroll
            for (int mi = 0; mi < 4; mi++)
                ldsm_x4(af[mi], sA0 + (wm + mi * 16) * ROWB + ko + aoff);
            // pass 0: Ahi * Bhi
            #pragma unroll
            for (int mi = 0; mi < 4; mi++)
                #pragma unroll
                for (int ni = 0; ni < 4; ni++)
                    mma_bf16(acc[mi][ni], af[mi], &bh[ni >> 1][(ni & 1) * 2]);
            // pass 1: Ahi * Blo (reuse af)
            #pragma unroll
            for (int mi = 0; mi < 4; mi++)
                #pragma unroll
                for (int ni = 0; ni < 4; ni++)
                    mma_bf16(acc[mi][ni], af[mi], &bl[ni >> 1][(ni & 1) * 2]);
            // A-lo frags (overwrite af)
            #pragma unroll
            for (int mi = 0; mi < 4; mi++)
                ldsm_x4(af[mi], sA1 + (wm + mi * 16) * ROWB + ko + aoff);
            // pass 2: Alo * Bhi
            #pragma unroll
            for (int mi = 0; mi < 4; mi++)
                #pragma unroll
                for (int ni = 0; ni < 4; ni++)
                    mma_bf16(acc[mi][ni], af[mi], &bh[ni >> 1][(ni & 1) * 2]);
        }
        __syncthreads();
        if (ch + 2 < nch) LOAD_STAGE(ch & 1, (ch0 + ch + 2) * 32)
    }

    // ---- epilogue: fragment layout -> global fp32 ----
    const int rr = lane >> 2;
    const int cc = (lane & 3) * 2;
    #pragma unroll
    for (int mi = 0; mi < 4; mi++) {
        int grow = bm * 128 + wm + mi * 16 + rr;
        #pragma unroll
        for (int ni = 0; ni < 4; ni++) {
            int gcol = bn * 128 + wn + ni * 8 + cc;
            *(float2*)&C[(size_t)grow * ldc + gcol] =
                make_float2(acc[mi][ni][0], acc[mi][ni][1]);
            *(float2*)&C[(size_t)(grow + 8) * ldc + gcol] =
                make_float2(acc[mi][ni][2], acc[mi][ni][3]);
        }
    }
    #undef LOAD_STAGE
}

// ---- merged logits GEMM: z=0 -> speech/svm, z=1 -> face/fkm --------------
__global__ __launch_bounds__(256, 2) void gemm_logits_k(
    const __nv_bfloat16* __restrict__ Shi, const __nv_bfloat16* __restrict__ Slo,
    const __nv_bfloat16* __restrict__ Vhi, const __nv_bfloat16* __restrict__ Vlo,
    const __nv_bfloat16* __restrict__ Fhi, const __nv_bfloat16* __restrict__ Flo,
    const __nv_bfloat16* __restrict__ Khi, const __nv_bfloat16* __restrict__ Klo,
    float* __restrict__ C) {
    const int z = blockIdx.z;
    const __nv_bfloat16* A0 = z ? Fhi : Shi;
    const __nv_bfloat16* A1 = z ? Flo : Slo;
    const __nv_bfloat16* B0 = z ? Khi : Vhi;
    const __nv_bfloat16* B1 = z ? Klo : Vlo;
    float* Cz = C + (size_t)z * N_ROWS * S_ROWS;
    gemm3_body(A0, A1, B0, B1, Cz, C_DIM, S_ROWS, 0, C_DIM / 32,
               blockIdx.y, blockIdx.x);
}

// ---- merged recall GEMM with split-K=2: M=16384, partials to g_part ------
__global__ __launch_bounds__(256, 2) void gemm_recall_k(
    const __nv_bfloat16* __restrict__ Phi, const __nv_bfloat16* __restrict__ Plo,
    const __nv_bfloat16* __restrict__ Vthi, const __nv_bfloat16* __restrict__ Vtlo,
    float* __restrict__ part) {
    const int z = blockIdx.z;                       // K half
    float* Cz = part + (size_t)z * 2 * N_ROWS * C_DIM;
    gemm3_body(Phi, Plo, Vthi, Vtlo, Cz, S_ROWS, C_DIM,
               z * 64, 64, blockIdx.y, blockIdx.x);
}

// ---- reduce split-K partials and scatter to the two recall outputs -------
__global__ __launch_bounds__(256) void reduce_recall_k(const float* __restrict__ part,
                                                       float* __restrict__ outS,
                                                       float* __restrict__ outF) {
    const size_t i = ((size_t)blockIdx.x * 256 + threadIdx.x) * 4;  // over 16384*256 floats
    float4 a = *(const float4*)&part[i];
    float4 b = *(const float4*)&part[i + (size_t)2 * N_ROWS * C_DIM];
    a.x += b.x; a.y += b.y; a.z += b.z; a.w += b.w;
    const size_t half = (size_t)N_ROWS * C_DIM;
    if (i < half) *(float4*)&outS[i] = a;
    else          *(float4*)&outF[i - half] = a;
}

// ---------------- launch ---------------------------------------------------
extern "C" void kernel_launch(void* const* d_in, const int* in_sizes, int n_in,
                              void* d_out, int out_size) {
    const float* face   = (const float*)d_in[0];
    const float* speech = (const float*)d_in[1];
    const float* svm    = (const float*)d_in[2];
    const float* fkm    = (const float*)d_in[3];
    float* out = (float*)d_out;

    __nv_bfloat16 *Shi, *Slo, *Fhi, *Flo, *Vhi, *Vlo, *Khi, *Klo, *Vthi, *Vtlo, *Phi, *Plo;
    float* Part;
    cudaGetSymbolAddress((void**)&Shi, g_Shi);  cudaGetSymbolAddress((void**)&Slo, g_Slo);
    cudaGetSymbolAddress((void**)&Fhi, g_Fhi);  cudaGetSymbolAddress((void**)&Flo, g_Flo);
    cudaGetSymbolAddress((void**)&Vhi, g_Vhi);  cudaGetSymbolAddress((void**)&Vlo, g_Vlo);
    cudaGetSymbolAddress((void**)&Khi, g_Khi);  cudaGetSymbolAddress((void**)&Klo, g_Klo);
    cudaGetSymbolAddress((void**)&Vthi, g_Vthi); cudaGetSymbolAddress((void**)&Vtlo, g_Vtlo);
    cudaGetSymbolAddress((void**)&Phi, g_Phi);  cudaGetSymbolAddress((void**)&Plo, g_Plo);
    cudaGetSymbolAddress((void**)&Part, g_part);

    const size_t o_se  = 0;
    const size_t o_ser = 2097152;
    const size_t o_fe  = 4194304;
    const size_t o_fer = 6291456;
    const size_t o_sal = 8388608;

    cudaMemcpyAsync(out + o_se, speech, (size_t)N_ROWS * C_DIM * sizeof(float),
                    cudaMemcpyDeviceToDevice, 0);
    cudaMemcpyAsync(out + o_fe, face, (size_t)N_ROWS * C_DIM * sizeof(float),
                    cudaMemcpyDeviceToDevice, 0);

    cudaFuncSetAttribute(gemm_logits_k, cudaFuncAttributeMaxDynamicSharedMemorySize, GEMM_SMEM);
    cudaFuncSetAttribute(gemm_recall_k, cudaFuncAttributeMaxDynamicSharedMemorySize, GEMM_SMEM);

    // prep (3 kernels so gemm_logits_k is the 6th op incl. the 2 memcpys)
    norm_emb_k<<<2 * N_ROWS, 256>>>(speech, face, Shi, Slo, Fhi, Flo);
    norm_mem_k<<<2 * S_ROWS, 256>>>(svm, fkm, Vhi, Vlo, Khi, Klo);
    transpose_split_k<<<dim3(C_DIM / 32, S_ROWS / 32), dim3(32, 8)>>>(svm, Vthi, Vtlo);

    // merged logits GEMM: [2][8192,4096] = A[8192,256] x B[4096,256]^T
    gemm_logits_k<<<dim3(32, 64, 2), 256, GEMM_SMEM>>>(Shi, Slo, Vhi, Vlo,
                                                       Fhi, Flo, Khi, Klo, out + o_sal);

    // log-softmax (in place) + P = exp(logsm) split bf16 over both matrices
    softmax_rows_k<<<2 * N_ROWS, 256>>>(out + o_sal, Phi, Plo);

    // merged recall GEMM (M=16384) with split-K=2 -> partials, then reduce
    gemm_recall_k<<<dim3(2, 128, 2), 256, GEMM_SMEM>>>(Phi, Plo, Vthi, Vtlo, Part);
    reduce_recall_k<<<(2 * N_ROWS * C_DIM) / (256 * 4), 256>>>(Part, out + o_ser, out + o_fer);
}

// round 13
// speedup vs baseline: 2.9629x; 1.1301x over previous
#include <cuda_runtime.h>
#include <cuda_bf16.h>
#include <cstdint>

#define N_ROWS 8192
#define S_ROWS 4096
#define C_DIM  256

// ---------------- scratch (static device arrays; no runtime allocation) ----
__device__ __align__(16) __nv_bfloat16 g_Shi[N_ROWS * C_DIM], g_Slo[N_ROWS * C_DIM];
__device__ __align__(16) __nv_bfloat16 g_Fhi[N_ROWS * C_DIM], g_Flo[N_ROWS * C_DIM];
__device__ __align__(16) __nv_bfloat16 g_Vhi[S_ROWS * C_DIM], g_Vlo[S_ROWS * C_DIM];
__device__ __align__(16) __nv_bfloat16 g_Khi[S_ROWS * C_DIM], g_Klo[S_ROWS * C_DIM];
__device__ __align__(16) __nv_bfloat16 g_Vthi[C_DIM * S_ROWS], g_Vtlo[C_DIM * S_ROWS];
__device__ __align__(16) __nv_bfloat16 g_Phi[(size_t)2 * N_ROWS * S_ROWS];
__device__ __align__(16) __nv_bfloat16 g_Plo[(size_t)2 * N_ROWS * S_ROWS];
// split-K partials for merged recall GEMM: [2 splits][16384, 256] fp32
__device__ __align__(16) float g_part[(size_t)2 * 2 * N_ROWS * C_DIM];

// ---------------- fast exp on FMA pipe ------------------------------------
__device__ __forceinline__ float fexp(float x) {
    x = fmaxf(x, -80.0f);
    float z = fmaf(x, 1.4426950408889634f, 12582912.0f);
    float n = z - 12582912.0f;
    float r = fmaf(n, -0.69314718055994531f, x);
    float p = 1.3888889e-3f;
    p = fmaf(p, r, 8.3333333e-3f);
    p = fmaf(p, r, 4.1666667e-2f);
    p = fmaf(p, r, 1.6666667e-1f);
    p = fmaf(p, r, 0.5f);
    p = fmaf(p, r, 1.0f);
    p = fmaf(p, r, 1.0f);
    int e = (int)n;
    return p * __int_as_float((e + 127) << 23);
}

// ---------------- row normalize + hi/lo split core ------------------------
__device__ __forceinline__ void norm_row(const float* __restrict__ x,
                                         __nv_bfloat16* __restrict__ hi,
                                         __nv_bfloat16* __restrict__ lo,
                                         int row, int t) {
    __shared__ float warpred[8];
    __shared__ float rn_s;
    float v = x[(size_t)row * C_DIM + t];
    float s = v * v;
    #pragma unroll
    for (int o = 16; o > 0; o >>= 1) s += __shfl_xor_sync(0xffffffffu, s, o);
    if ((t & 31) == 0) warpred[t >> 5] = s;
    __syncthreads();
    if (t == 0) {
        float tot = 0.f;
        #pragma unroll
        for (int i = 0; i < 8; i++) tot += warpred[i];
        rn_s = rsqrtf(tot);
    }
    __syncthreads();
    float y = v * rn_s;
    __nv_bfloat16 h = __float2bfloat16(y);
    hi[(size_t)row * C_DIM + t] = h;
    lo[(size_t)row * C_DIM + t] = __float2bfloat16(y - __bfloat162float(h));
}

// merged embedding normalize: rows [0,8192) speech, [8192,16384) face
__global__ __launch_bounds__(256) void norm_emb_k(const float* __restrict__ speech,
                                                  const float* __restrict__ face,
                                                  __nv_bfloat16* __restrict__ Shi,
                                                  __nv_bfloat16* __restrict__ Slo,
                                                  __nv_bfloat16* __restrict__ Fhi,
                                                  __nv_bfloat16* __restrict__ Flo) {
    const int b = blockIdx.x;
    if (b < N_ROWS) norm_row(speech, Shi, Slo, b, threadIdx.x);
    else            norm_row(face, Fhi, Flo, b - N_ROWS, threadIdx.x);
}

// merged memory normalize: rows [0,4096) svm, [4096,8192) fkm
__global__ __launch_bounds__(256) void norm_mem_k(const float* __restrict__ svm,
                                                  const float* __restrict__ fkm,
                                                  __nv_bfloat16* __restrict__ Vhi,
                                                  __nv_bfloat16* __restrict__ Vlo,
                                                  __nv_bfloat16* __restrict__ Khi,
                                                  __nv_bfloat16* __restrict__ Klo) {
    const int b = blockIdx.x;
    if (b < S_ROWS) norm_row(svm, Vhi, Vlo, b, threadIdx.x);
    else            norm_row(fkm, Khi, Klo, b - S_ROWS, threadIdx.x);
}

// ---------------- transpose raw svm [4096,256] -> [256,4096] hi/lo --------
__global__ void transpose_split_k(const float* __restrict__ V,
                                  __nv_bfloat16* __restrict__ Thi,
                                  __nv_bfloat16* __restrict__ Tlo) {
    __shared__ float ts[32][33];
    const int tx = threadIdx.x, ty = threadIdx.y;          // 32 x 8
    const int n0 = blockIdx.x * 32, k0 = blockIdx.y * 32;
    #pragma unroll
    for (int j = 0; j < 4; j++)
        ts[ty + 8 * j][tx] = V[(size_t)(k0 + ty + 8 * j) * C_DIM + n0 + tx];
    __syncthreads();
    #pragma unroll
    for (int j = 0; j < 4; j++) {
        int n = n0 + ty + 8 * j;
        int k = k0 + tx;
        float v = ts[tx][ty + 8 * j];
        __nv_bfloat16 h = __float2bfloat16(v);
        Thi[(size_t)n * S_ROWS + k] = h;
        Tlo[(size_t)n * S_ROWS + k] = __float2bfloat16(v - __bfloat162float(h));
    }
}

// ---------------- in-place log-softmax + P=exp(logsm) hi/lo ---------------
__global__ __launch_bounds__(256) void softmax_rows_k(float* __restrict__ base,
                                                      __nv_bfloat16* __restrict__ Phi,
                                                      __nv_bfloat16* __restrict__ Plo) {
    __shared__ float warpred[8];
    __shared__ float bc;
    const size_t rbase = (size_t)blockIdx.x * 4096;
    float* p = base + rbase;
    const int t = threadIdx.x;
    float x[16];
    #pragma unroll
    for (int i = 0; i < 4; i++) {
        float4 v = *(const float4*)&p[i * 1024 + t * 4];
        x[i * 4 + 0] = v.x; x[i * 4 + 1] = v.y; x[i * 4 + 2] = v.z; x[i * 4 + 3] = v.w;
    }
    float mx = x[0];
    #pragma unroll
    for (int i = 1; i < 16; i++) mx = fmaxf(mx, x[i]);
    #pragma unroll
    for (int o = 16; o > 0; o >>= 1) mx = fmaxf(mx, __shfl_xor_sync(0xffffffffu, mx, o));
    if ((t & 31) == 0) warpred[t >> 5] = mx;
    __syncthreads();
    if (t == 0) {
        float m = warpred[0];
        #pragma unroll
        for (int i = 1; i < 8; i++) m = fmaxf(m, warpred[i]);
        bc = m;
    }
    __syncthreads();
    mx = bc;
    __syncthreads();
    float s = 0.f;
    #pragma unroll
    for (int i = 0; i < 16; i++) s += fexp(x[i] - mx);
    #pragma unroll
    for (int o = 16; o > 0; o >>= 1) s += __shfl_xor_sync(0xffffffffu, s, o);
    if ((t & 31) == 0) warpred[t >> 5] = s;
    __syncthreads();
    if (t == 0) {
        float tot = 0.f;
        #pragma unroll
        for (int i = 0; i < 8; i++) tot += warpred[i];
        bc = mx + logf(tot);
    }
    __syncthreads();
    const float lse = bc;
    #pragma unroll
    for (int i = 0; i < 4; i++) {
        float l0 = x[i * 4 + 0] - lse, l1 = x[i * 4 + 1] - lse;
        float l2 = x[i * 4 + 2] - lse, l3 = x[i * 4 + 3] - lse;
        *(float4*)&p[i * 1024 + t * 4] = make_float4(l0, l1, l2, l3);
        float p0 = fexp(l0), p1 = fexp(l1), p2 = fexp(l2), p3 = fexp(l3);
        __nv_bfloat16 h0 = __float2bfloat16(p0), h1 = __float2bfloat16(p1);
        __nv_bfloat16 h2 = __float2bfloat16(p2), h3 = __float2bfloat16(p3);
        __nv_bfloat162 a; a.x = h0; a.y = h1;
        __nv_bfloat162 b; b.x = h2; b.y = h3;
        *(__nv_bfloat162*)&Phi[rbase + i * 1024 + t * 4] = a;
        *(__nv_bfloat162*)&Phi[rbase + i * 1024 + t * 4 + 2] = b;
        __nv_bfloat162 c, d;
        c.x = __float2bfloat16(p0 - __bfloat162float(h0));
        c.y = __float2bfloat16(p1 - __bfloat162float(h1));
        d.x = __float2bfloat16(p2 - __bfloat162float(h2));
        d.y = __float2bfloat16(p3 - __bfloat162float(h3));
        *(__nv_bfloat162*)&Plo[rbase + i * 1024 + t * 4] = c;
        *(__nv_bfloat162*)&Plo[rbase + i * 1024 + t * 4 + 2] = d;
    }
}

// =================== HMMA split-bf16 GEMM body =============================
// C[M,N] += over k-range: (Ahi+Alo)(Bhi+Blo)^T via 3 passes
// (hi*hi + hi*lo + lo*hi), fp32 accumulate.
// A:[M,K] bf16 row-major, B:[N,K] bf16 row-major.
// CTA tile 128x128, BK=32, 8 warps (warp tile 64x32), 2-stage cp.async.
// smem rows padded to 80B (5 x 16B chunks) -> conflict-free ldmatrix.
// Chunk structure keeps the tensor queue fed across the stage barrier:
// the barrier sits after ALL smem reads of the chunk but BEFORE the last
// 32 register-only MMAs, so the HMMA pipe never drains at chunk boundaries.

#define ROWB 80             // bytes per smem row (32 bf16 data + 8 pad)
#define TILEB (128 * ROWB)  // 10240 B per operand tile
#define STAGEB (4 * TILEB)  // Ahi,Alo,Bhi,Blo = 40960 B
#define GEMM_SMEM (2 * STAGEB)  // 81920

__device__ __forceinline__ void cp16(uint32_t d, const void* g) {
    asm volatile("cp.async.cg.shared.global [%0], [%1], 16;" :: "r"(d), "l"(g) : "memory");
}
__device__ __forceinline__ void ldsm_x4(uint32_t* r, uint32_t a) {
    asm volatile("ldmatrix.sync.aligned.m8n8.x4.shared.b16 {%0,%1,%2,%3}, [%4];"
                 : "=r"(r[0]), "=r"(r[1]), "=r"(r[2]), "=r"(r[3]) : "r"(a));
}
__device__ __forceinline__ void mma_bf16(float* d, const uint32_t* a, const uint32_t* b) {
    asm volatile(
        "mma.sync.aligned.m16n8k16.row.col.f32.bf16.bf16.f32 "
        "{%0,%1,%2,%3},{%4,%5,%6,%7},{%8,%9},{%0,%1,%2,%3};"
        : "+f"(d[0]), "+f"(d[1]), "+f"(d[2]), "+f"(d[3])
        : "r"(a[0]), "r"(a[1]), "r"(a[2]), "r"(a[3]), "r"(b[0]), "r"(b[1]));
}

__device__ __forceinline__ void gemm3_body(
    const __nv_bfloat16* __restrict__ Ahi, const __nv_bfloat16* __restrict__ Alo,
    const __nv_bfloat16* __restrict__ Bhi, const __nv_bfloat16* __restrict__ Blo,
    float* __restrict__ C, int K, int ldc, int ch0, int nch, int bm, int bn) {
    extern __shared__ char smem[];
    uint32_t sb;
    asm("{ .reg .u64 t; cvta.to.shared.u64 t, %1; cvt.u32.u64 %0, t; }" : "=r"(sb) : "l"(smem));
    const int tid = threadIdx.x;
    const int wid = tid >> 5, lane = tid & 31;
    const int wm = (wid >> 2) * 64;   // warp row base within CTA tile
    const int wn = (wid & 3) * 32;    // warp col base

    const __nv_bfloat16* gA0 = Ahi + (size_t)bm * 128 * K;
    const __nv_bfloat16* gA1 = Alo + (size_t)bm * 128 * K;
    const __nv_bfloat16* gB0 = Bhi + (size_t)bn * 128 * K;
    const __nv_bfloat16* gB1 = Blo + (size_t)bn * 128 * K;

    // per-thread cp.async assignment: q in [0,512): row=q>>2, 16B-chunk=q&3
    const int r0 = tid >> 2, c0 = (tid & 3);
    const int r1 = (tid + 256) >> 2, c1 = ((tid + 256) & 3);

    // ldmatrix per-lane offsets
    // A x4: lanes 0-7 mat0 rows, 8-15 mat1 rows (+8), 16-31 k+16B halves
    const uint32_t aoff = (uint32_t)(((lane & 7) + ((lane >> 3) & 1) * 8) * ROWB
                                     + (lane >> 4) * 16);
    // B x4 (two n8 groups per instr): lanes 0-7 mat0 (n rows, k0), 8-15 mat1 (k+16B),
    // 16-23 mat2 (n rows +8, k0), 24-31 mat3 (n+8, k+16B)
    const uint32_t boff4 = (uint32_t)(((lane >> 4) * 8 + (lane & 7)) * ROWB
                                      + ((lane >> 3) & 1) * 16);

    float acc[4][4][4];
    #pragma unroll
    for (int mi = 0; mi < 4; mi++)
        #pragma unroll
        for (int ni = 0; ni < 4; ni++)
            #pragma unroll
            for (int e = 0; e < 4; e++) acc[mi][ni][e] = 0.f;

    // ---- stage loader ----
    #define LOAD_STAGE(s, k0)                                                   \
    {                                                                           \
        uint32_t base = sb + (s) * STAGEB;                                      \
        size_t ga = (size_t)r0 * K + (k0) + c0 * 8;                             \
        uint32_t da = base + (uint32_t)(r0 * ROWB + c0 * 16);                   \
        cp16(da,              gA0 + ga);                                        \
        cp16(da + TILEB,      gA1 + ga);                                        \
        cp16(da + 2 * TILEB,  gB0 + ga);                                        \
        cp16(da + 3 * TILEB,  gB1 + ga);                                        \
        size_t gb = (size_t)r1 * K + (k0) + c1 * 8;                             \
        uint32_t db = base + (uint32_t)(r1 * ROWB + c1 * 16);                   \
        cp16(db,              gA0 + gb);                                        \
        cp16(db + TILEB,      gA1 + gb);                                        \
        cp16(db + 2 * TILEB,  gB0 + gb);                                        \
        cp16(db + 3 * TILEB,  gB1 + gb);                                        \
        asm volatile("cp.async.commit_group;" ::: "memory");                    \
    }

    LOAD_STAGE(0, ch0 * 32)
    if (nch > 1) LOAD_STAGE(1, (ch0 + 1) * 32)

    for (int ch = 0; ch < nch; ch++) {
        if (ch + 1 < nch) {
            asm volatile("cp.async.wait_group 1;" ::: "memory");
        } else {
            asm volatile("cp.async.wait_group 0;" ::: "memory");
        }
        __syncthreads();

        uint32_t stg = sb + (uint32_t)(ch & 1) * STAGEB;
        uint32_t sA0 = stg;
        uint32_t sA1 = stg + TILEB;
        uint32_t sB0 = stg + 2 * TILEB;
        uint32_t sB1 = stg + 3 * TILEB;
        const bool prefetch = (ch + 2 < nch);

        uint32_t af[4][4], bh[2][4], bl[2][4];

        // ================= ks = 0 (ko = 0) =================
        #pragma unroll
        for (int g = 0; g < 2; g++) {
            ldsm_x4(bh[g], sB0 + (wn + g * 16) * ROWB + boff4);
            ldsm_x4(bl[g], sB1 + (wn + g * 16) * ROWB + boff4);
        }
        #pragma unroll
        for (int mi = 0; mi < 4; mi++)
            ldsm_x4(af[mi], sA0 + (wm + mi * 16) * ROWB + aoff);
        // Ahi * Bhi
        #pragma unroll
        for (int mi = 0; mi < 4; mi++)
            #pragma unroll
            for (int ni = 0; ni < 4; ni++)
                mma_bf16(acc[mi][ni], af[mi], &bh[ni >> 1][(ni & 1) * 2]);
        // Ahi * Blo
        #pragma unroll
        for (int mi = 0; mi < 4; mi++)
            #pragma unroll
            for (int ni = 0; ni < 4; ni++)
                mma_bf16(acc[mi][ni], af[mi], &bl[ni >> 1][(ni & 1) * 2]);
        // Alo * Bhi
        #pragma unroll
        for (int mi = 0; mi < 4; mi++)
            ldsm_x4(af[mi], sA1 + (wm + mi * 16) * ROWB + aoff);
        #pragma unroll
        for (int mi = 0; mi < 4; mi++)
            #pragma unroll
            for (int ni = 0; ni < 4; ni++)
                mma_bf16(acc[mi][ni], af[mi], &bh[ni >> 1][(ni & 1) * 2]);

        // ================= ks = 1 (ko = 32) =================
        #pragma unroll
        for (int g = 0; g < 2; g++) {
            ldsm_x4(bh[g], sB0 + (wn + g * 16) * ROWB + 32 + boff4);
            ldsm_x4(bl[g], sB1 + (wn + g * 16) * ROWB + 32 + boff4);
        }
        // Alo first, so the final two passes need no smem
        #pragma unroll
        for (int mi = 0; mi < 4; mi++)
            ldsm_x4(af[mi], sA1 + (wm + mi * 16) * ROWB + 32 + aoff);
        // Alo * Bhi
        #pragma unroll
        for (int mi = 0; mi < 4; mi++)
            #pragma unroll
            for (int ni = 0; ni < 4; ni++)
                mma_bf16(acc[mi][ni], af[mi], &bh[ni >> 1][(ni & 1) * 2]);
        // last smem reads of this chunk
        #pragma unroll
        for (int mi = 0; mi < 4; mi++)
            ldsm_x4(af[mi], sA0 + (wm + mi * 16) * ROWB + 32 + aoff);

        if (prefetch) {
            __syncthreads();                 // all smem reads of chunk done
            LOAD_STAGE(ch & 1, (ch0 + ch + 2) * 32)
        }

        // register-only MMAs cover the barrier/prefetch window
        // Ahi * Bhi
        #pragma unroll
        for (int mi = 0; mi < 4; mi++)
            #pragma unroll
            for (int ni = 0; ni < 4; ni++)
                mma_bf16(acc[mi][ni], af[mi], &bh[ni >> 1][(ni & 1) * 2]);
        // Ahi * Blo
        #pragma unroll
        for (int mi = 0; mi < 4; mi++)
            #pragma unroll
            for (int ni = 0; ni < 4; ni++)
                mma_bf16(acc[mi][ni], af[mi], &bl[ni >> 1][(ni & 1) * 2]);

        if (!prefetch && ch + 1 < nch) __syncthreads();  // protect stage reuse
    }

    // ---- epilogue: fragment layout -> global fp32 ----
    const int rr = lane >> 2;
    const int cc = (lane & 3) * 2;
    #pragma unroll
    for (int mi = 0; mi < 4; mi++) {
        int grow = bm * 128 + wm + mi * 16 + rr;
        #pragma unroll
        for (int ni = 0; ni < 4; ni++) {
            int gcol = bn * 128 + wn + ni * 8 + cc;
            *(float2*)&C[(size_t)grow * ldc + gcol] =
                make_float2(acc[mi][ni][0], acc[mi][ni][1]);
            *(float2*)&C[(size_t)(grow + 8) * ldc + gcol] =
                make_float2(acc[mi][ni][2], acc[mi][ni][3]);
        }
    }
    #undef LOAD_STAGE
}

// ---- merged logits GEMM: z=0 -> speech/svm, z=1 -> face/fkm --------------
__global__ __launch_bounds__(256, 2) void gemm_logits_k(
    const __nv_bfloat16* __restrict__ Shi, const __nv_bfloat16* __restrict__ Slo,
    const __nv_bfloat16* __restrict__ Vhi, const __nv_bfloat16* __restrict__ Vlo,
    const __nv_bfloat16* __restrict__ Fhi, const __nv_bfloat16* __restrict__ Flo,
    const __nv_bfloat16* __restrict__ Khi, const __nv_bfloat16* __restrict__ Klo,
    float* __restrict__ C) {
    const int z = blockIdx.z;
    const __nv_bfloat16* A0 = z ? Fhi : Shi;
    const __nv_bfloat16* A1 = z ? Flo : Slo;
    const __nv_bfloat16* B0 = z ? Khi : Vhi;
    const __nv_bfloat16* B1 = z ? Klo : Vlo;
    float* Cz = C + (size_t)z * N_ROWS * S_ROWS;
    gemm3_body(A0, A1, B0, B1, Cz, C_DIM, S_ROWS, 0, C_DIM / 32,
               blockIdx.y, blockIdx.x);
}

// ---- merged recall GEMM with split-K=2: M=16384, partials to g_part ------
__global__ __launch_bounds__(256, 2) void gemm_recall_k(
    const __nv_bfloat16* __restrict__ Phi, const __nv_bfloat16* __restrict__ Plo,
    const __nv_bfloat16* __restrict__ Vthi, const __nv_bfloat16* __restrict__ Vtlo,
    float* __restrict__ part) {
    const int z = blockIdx.z;                       // K half
    float* Cz = part + (size_t)z * 2 * N_ROWS * C_DIM;
    gemm3_body(Phi, Plo, Vthi, Vtlo, Cz, S_ROWS, C_DIM,
               z * 64, 64, blockIdx.y, blockIdx.x);
}

// ---- reduce split-K partials and scatter to the two recall outputs -------
__global__ __launch_bounds__(256) void reduce_recall_k(const float* __restrict__ part,
                                                       float* __restrict__ outS,
                                                       float* __restrict__ outF) {
    const size_t i = ((size_t)blockIdx.x * 256 + threadIdx.x) * 4;  // over 16384*256 floats
    float4 a = *(const float4*)&part[i];
    float4 b = *(const float4*)&part[i + (size_t)2 * N_ROWS * C_DIM];
    a.x += b.x; a.y += b.y; a.z += b.z; a.w += b.w;
    const size_t half = (size_t)N_ROWS * C_DIM;
    if (i < half) *(float4*)&outS[i] = a;
    else          *(float4*)&outF[i - half] = a;
}

// ---------------- launch ---------------------------------------------------
extern "C" void kernel_launch(void* const* d_in, const int* in_sizes, int n_in,
                              void* d_out, int out_size) {
    const float* face   = (const float*)d_in[0];
    const float* speech = (const float*)d_in[1];
    const float* svm    = (const float*)d_in[2];
    const float* fkm    = (const float*)d_in[3];
    float* out = (float*)d_out;

    __nv_bfloat16 *Shi, *Slo, *Fhi, *Flo, *Vhi, *Vlo, *Khi, *Klo, *Vthi, *Vtlo, *Phi, *Plo;
    float* Part;
    cudaGetSymbolAddress((void**)&Shi, g_Shi);  cudaGetSymbolAddress((void**)&Slo, g_Slo);
    cudaGetSymbolAddress((void**)&Fhi, g_Fhi);  cudaGetSymbolAddress((void**)&Flo, g_Flo);
    cudaGetSymbolAddress((void**)&Vhi, g_Vhi);  cudaGetSymbolAddress((void**)&Vlo, g_Vlo);
    cudaGetSymbolAddress((void**)&Khi, g_Khi);  cudaGetSymbolAddress((void**)&Klo, g_Klo);
    cudaGetSymbolAddress((void**)&Vthi, g_Vthi); cudaGetSymbolAddress((void**)&Vtlo, g_Vtlo);
    cudaGetSymbolAddress((void**)&Phi, g_Phi);  cudaGetSymbolAddress((void**)&Plo, g_Plo);
    cudaGetSymbolAddress((void**)&Part, g_part);

    const size_t o_se  = 0;
    const size_t o_ser = 2097152;
    const size_t o_fe  = 4194304;
    const size_t o_fer = 6291456;
    const size_t o_sal = 8388608;

    cudaMemcpyAsync(out + o_se, speech, (size_t)N_ROWS * C_DIM * sizeof(float),
                    cudaMemcpyDeviceToDevice, 0);
    cudaMemcpyAsync(out + o_fe, face, (size_t)N_ROWS * C_DIM * sizeof(float),
                    cudaMemcpyDeviceToDevice, 0);

    cudaFuncSetAttribute(gemm_logits_k, cudaFuncAttributeMaxDynamicSharedMemorySize, GEMM_SMEM);
    cudaFuncSetAttribute(gemm_recall_k, cudaFuncAttributeMaxDynamicSharedMemorySize, GEMM_SMEM);

    // prep (3 kernels so gemm_logits_k is the 6th op incl. the 2 memcpys)
    norm_emb_k<<<2 * N_ROWS, 256>>>(speech, face, Shi, Slo, Fhi, Flo);
    norm_mem_k<<<2 * S_ROWS, 256>>>(svm, fkm, Vhi, Vlo, Khi, Klo);
    transpose_split_k<<<dim3(C_DIM / 32, S_ROWS / 32), dim3(32, 8)>>>(svm, Vthi, Vtlo);

    // merged logits GEMM: [2][8192,4096] = A[8192,256] x B[4096,256]^T
    gemm_logits_k<<<dim3(32, 64, 2), 256, GEMM_SMEM>>>(Shi, Slo, Vhi, Vlo,
                                                       Fhi, Flo, Khi, Klo, out + o_sal);

    // log-softmax (in place) + P = exp(logsm) split bf16 over both matrices
    softmax_rows_k<<<2 * N_ROWS, 256>>>(out + o_sal, Phi, Plo);

    // merged recall GEMM (M=16384) with split-K=2 -> partials, then reduce
    gemm_recall_k<<<dim3(2, 128, 2), 256, GEMM_SMEM>>>(Phi, Plo, Vthi, Vtlo, Part);
    reduce_recall_k<<<(2 * N_ROWS * C_DIM) / (256 * 4), 256>>>(Part, out + o_ser, out + o_fer);
}

// round 14
// speedup vs baseline: 5.1841x; 1.7497x over previous
#include <cuda_runtime.h>
#include <cuda_fp16.h>
#include <cstdint>

#define N_ROWS 8192
#define S_ROWS 4096
#define C_DIM  256

// ---------------- scratch (static device arrays; no runtime allocation) ----
__device__ __align__(16) __half g_Sh[N_ROWS * C_DIM];
__device__ __align__(16) __half g_Fh[N_ROWS * C_DIM];
__device__ __align__(16) __half g_Vh[S_ROWS * C_DIM];
__device__ __align__(16) __half g_Kh[S_ROWS * C_DIM];
__device__ __align__(16) __half g_Vth[C_DIM * S_ROWS];
__device__ __align__(16) __half g_Ph[(size_t)2 * N_ROWS * S_ROWS];
// split-K partials for merged recall GEMM: [2 splits][16384, 256] fp32
__device__ __align__(16) float g_part[(size_t)2 * 2 * N_ROWS * C_DIM];

// ---------------- fast exp on FMA pipe ------------------------------------
__device__ __forceinline__ float fexp(float x) {
    x = fmaxf(x, -80.0f);
    float z = fmaf(x, 1.4426950408889634f, 12582912.0f);
    float n = z - 12582912.0f;
    float r = fmaf(n, -0.69314718055994531f, x);
    float p = 1.3888889e-3f;
    p = fmaf(p, r, 8.3333333e-3f);
    p = fmaf(p, r, 4.1666667e-2f);
    p = fmaf(p, r, 1.6666667e-1f);
    p = fmaf(p, r, 0.5f);
    p = fmaf(p, r, 1.0f);
    p = fmaf(p, r, 1.0f);
    int e = (int)n;
    return p * __int_as_float((e + 127) << 23);
}

// ---------------- row normalize -> fp16 -----------------------------------
__device__ __forceinline__ void norm_row(const float* __restrict__ x,
                                         __half* __restrict__ h,
                                         int row, int t) {
    __shared__ float warpred[8];
    __shared__ float rn_s;
    float v = x[(size_t)row * C_DIM + t];
    float s = v * v;
    #pragma unroll
    for (int o = 16; o > 0; o >>= 1) s += __shfl_xor_sync(0xffffffffu, s, o);
    if ((t & 31) == 0) warpred[t >> 5] = s;
    __syncthreads();
    if (t == 0) {
        float tot = 0.f;
        #pragma unroll
        for (int i = 0; i < 8; i++) tot += warpred[i];
        rn_s = rsqrtf(tot);
    }
    __syncthreads();
    h[(size_t)row * C_DIM + t] = __float2half_rn(v * rn_s);
}

// merged embedding normalize: rows [0,8192) speech, [8192,16384) face
__global__ __launch_bounds__(256) void norm_emb_k(const float* __restrict__ speech,
                                                  const float* __restrict__ face,
                                                  __half* __restrict__ Sh,
                                                  __half* __restrict__ Fh) {
    const int b = blockIdx.x;
    if (b < N_ROWS) norm_row(speech, Sh, b, threadIdx.x);
    else            norm_row(face, Fh, b - N_ROWS, threadIdx.x);
}

// merged memory normalize: rows [0,4096) svm, [4096,8192) fkm
__global__ __launch_bounds__(256) void norm_mem_k(const float* __restrict__ svm,
                                                  const float* __restrict__ fkm,
                                                  __half* __restrict__ Vh,
                                                  __half* __restrict__ Kh) {
    const int b = blockIdx.x;
    if (b < S_ROWS) norm_row(svm, Vh, b, threadIdx.x);
    else            norm_row(fkm, Kh, b - S_ROWS, threadIdx.x);
}

// ---------------- transpose raw svm [4096,256] -> [256,4096] fp16 ---------
__global__ void transpose_half_k(const float* __restrict__ V,
                                 __half* __restrict__ T) {
    __shared__ float ts[32][33];
    const int tx = threadIdx.x, ty = threadIdx.y;          // 32 x 8
    const int n0 = blockIdx.x * 32, k0 = blockIdx.y * 32;
    #pragma unroll
    for (int j = 0; j < 4; j++)
        ts[ty + 8 * j][tx] = V[(size_t)(k0 + ty + 8 * j) * C_DIM + n0 + tx];
    __syncthreads();
    #pragma unroll
    for (int j = 0; j < 4; j++) {
        int n = n0 + ty + 8 * j;
        int k = k0 + tx;
        T[(size_t)n * S_ROWS + k] = __float2half_rn(ts[tx][ty + 8 * j]);
    }
}

// ---------------- in-place log-softmax + P=exp(logsm) fp16 ----------------
__global__ __launch_bounds__(256) void softmax_rows_k(float* __restrict__ base,
                                                      __half* __restrict__ P) {
    __shared__ float warpred[8];
    __shared__ float bc;
    const size_t rbase = (size_t)blockIdx.x * 4096;
    float* p = base + rbase;
    const int t = threadIdx.x;
    float x[16];
    #pragma unroll
    for (int i = 0; i < 4; i++) {
        float4 v = *(const float4*)&p[i * 1024 + t * 4];
        x[i * 4 + 0] = v.x; x[i * 4 + 1] = v.y; x[i * 4 + 2] = v.z; x[i * 4 + 3] = v.w;
    }
    float mx = x[0];
    #pragma unroll
    for (int i = 1; i < 16; i++) mx = fmaxf(mx, x[i]);
    #pragma unroll
    for (int o = 16; o > 0; o >>= 1) mx = fmaxf(mx, __shfl_xor_sync(0xffffffffu, mx, o));
    if ((t & 31) == 0) warpred[t >> 5] = mx;
    __syncthreads();
    if (t == 0) {
        float m = warpred[0];
        #pragma unroll
        for (int i = 1; i < 8; i++) m = fmaxf(m, warpred[i]);
        bc = m;
    }
    __syncthreads();
    mx = bc;
    __syncthreads();
    float s = 0.f;
    #pragma unroll
    for (int i = 0; i < 16; i++) s += fexp(x[i] - mx);
    #pragma unroll
    for (int o = 16; o > 0; o >>= 1) s += __shfl_xor_sync(0xffffffffu, s, o);
    if ((t & 31) == 0) warpred[t >> 5] = s;
    __syncthreads();
    if (t == 0) {
        float tot = 0.f;
        #pragma unroll
        for (int i = 0; i < 8; i++) tot += warpred[i];
        bc = mx + logf(tot);
    }
    __syncthreads();
    const float lse = bc;
    #pragma unroll
    for (int i = 0; i < 4; i++) {
        float l0 = x[i * 4 + 0] - lse, l1 = x[i * 4 + 1] - lse;
        float l2 = x[i * 4 + 2] - lse, l3 = x[i * 4 + 3] - lse;
        *(float4*)&p[i * 1024 + t * 4] = make_float4(l0, l1, l2, l3);
        __half2 a, b;
        a.x = __float2half_rn(fexp(l0)); a.y = __float2half_rn(fexp(l1));
        b.x = __float2half_rn(fexp(l2)); b.y = __float2half_rn(fexp(l3));
        *(__half2*)&P[rbase + i * 1024 + t * 4] = a;
        *(__half2*)&P[rbase + i * 1024 + t * 4 + 2] = b;
    }
}

// =================== HMMA fp16 single-pass GEMM ============================
// C[M,N] += over k-range: A * B^T, fp32 accumulate.
// A:[M,K] fp16 row-major, B:[N,K] fp16 row-major.
// CTA tile 128x128, BK=32, 8 warps (warp tile 64x32), 2-stage cp.async.
// smem rows padded to 80B (4 x 16B data chunks + 16B pad) -> conflict-free
// ldmatrix. The stage barrier sits after ALL smem reads of the chunk but
// BEFORE the final 16 register-only MMAs, keeping the tensor queue fed.

#define ROWB 80             // bytes per smem row (32 fp16 data + 16B pad)
#define TILEB (128 * ROWB)  // 10240 B per operand tile
#define STAGEB (2 * TILEB)  // A,B = 20480 B
#define GEMM_SMEM (2 * STAGEB)  // 40960

__device__ __forceinline__ void cp16(uint32_t d, const void* g) {
    asm volatile("cp.async.cg.shared.global [%0], [%1], 16;" :: "r"(d), "l"(g) : "memory");
}
__device__ __forceinline__ void ldsm_x4(uint32_t* r, uint32_t a) {
    asm volatile("ldmatrix.sync.aligned.m8n8.x4.shared.b16 {%0,%1,%2,%3}, [%4];"
                 : "=r"(r[0]), "=r"(r[1]), "=r"(r[2]), "=r"(r[3]) : "r"(a));
}
__device__ __forceinline__ void mma_fp16(float* d, const uint32_t* a, const uint32_t* b) {
    asm volatile(
        "mma.sync.aligned.m16n8k16.row.col.f32.f16.f16.f32 "
        "{%0,%1,%2,%3},{%4,%5,%6,%7},{%8,%9},{%0,%1,%2,%3};"
        : "+f"(d[0]), "+f"(d[1]), "+f"(d[2]), "+f"(d[3])
        : "r"(a[0]), "r"(a[1]), "r"(a[2]), "r"(a[3]), "r"(b[0]), "r"(b[1]));
}

__device__ __forceinline__ void gemm1_body(
    const __half* __restrict__ A, const __half* __restrict__ B,
    float* __restrict__ C, int K, int ldc, int ch0, int nch, int bm, int bn) {
    extern __shared__ char smem[];
    uint32_t sb;
    asm("{ .reg .u64 t; cvta.to.shared.u64 t, %1; cvt.u32.u64 %0, t; }" : "=r"(sb) : "l"(smem));
    const int tid = threadIdx.x;
    const int wid = tid >> 5, lane = tid & 31;
    const int wm = (wid >> 2) * 64;   // warp row base within CTA tile
    const int wn = (wid & 3) * 32;    // warp col base

    const __half* gA = A + (size_t)bm * 128 * K;
    const __half* gB = B + (size_t)bn * 128 * K;

    // per-thread cp.async assignment: q in [0,512): row=q>>2, 16B-chunk=q&3
    const int r0 = tid >> 2, c0 = (tid & 3);
    const int r1 = (tid + 256) >> 2, c1 = ((tid + 256) & 3);

    // ldmatrix per-lane offsets
    const uint32_t aoff = (uint32_t)(((lane & 7) + ((lane >> 3) & 1) * 8) * ROWB
                                     + (lane >> 4) * 16);
    const uint32_t boff4 = (uint32_t)(((lane >> 4) * 8 + (lane & 7)) * ROWB
                                      + ((lane >> 3) & 1) * 16);

    float acc[4][4][4];
    #pragma unroll
    for (int mi = 0; mi < 4; mi++)
        #pragma unroll
        for (int ni = 0; ni < 4; ni++)
            #pragma unroll
            for (int e = 0; e < 4; e++) acc[mi][ni][e] = 0.f;

    // ---- stage loader ----
    #define LOAD_STAGE(s, k0)                                                   \
    {                                                                           \
        uint32_t base = sb + (s) * STAGEB;                                      \
        size_t ga = (size_t)r0 * K + (k0) + c0 * 8;                             \
        uint32_t da = base + (uint32_t)(r0 * ROWB + c0 * 16);                   \
        cp16(da,         gA + ga);                                              \
        cp16(da + TILEB, gB + ga);                                              \
        size_t gb = (size_t)r1 * K + (k0) + c1 * 8;                             \
        uint32_t db = base + (uint32_t)(r1 * ROWB + c1 * 16);                   \
        cp16(db,         gA + gb);                                              \
        cp16(db + TILEB, gB + gb);                                              \
        asm volatile("cp.async.commit_group;" ::: "memory");                    \
    }

    LOAD_STAGE(0, ch0 * 32)
    if (nch > 1) LOAD_STAGE(1, (ch0 + 1) * 32)

    for (int ch = 0; ch < nch; ch++) {
        if (ch + 1 < nch) {
            asm volatile("cp.async.wait_group 1;" ::: "memory");
        } else {
            asm volatile("cp.async.wait_group 0;" ::: "memory");
        }
        __syncthreads();

        uint32_t stg = sb + (uint32_t)(ch & 1) * STAGEB;
        uint32_t sA = stg;
        uint32_t sB = stg + TILEB;
        const bool prefetch = (ch + 2 < nch);

        uint32_t af[4][4], bf[2][4];

        // ================= ks = 0 (ko = 0) =================
        #pragma unroll
        for (int g = 0; g < 2; g++)
            ldsm_x4(bf[g], sB + (wn + g * 16) * ROWB + boff4);
        #pragma unroll
        for (int mi = 0; mi < 4; mi++)
            ldsm_x4(af[mi], sA + (wm + mi * 16) * ROWB + aoff);
        #pragma unroll
        for (int mi = 0; mi < 4; mi++)
            #pragma unroll
            for (int ni = 0; ni < 4; ni++)
                mma_fp16(acc[mi][ni], af[mi], &bf[ni >> 1][(ni & 1) * 2]);

        // ================= ks = 1 (ko = 32) =================
        #pragma unroll
        for (int g = 0; g < 2; g++)
            ldsm_x4(bf[g], sB + (wn + g * 16) * ROWB + 32 + boff4);
        #pragma unroll
        for (int mi = 0; mi < 4; mi++)
            ldsm_x4(af[mi], sA + (wm + mi * 16) * ROWB + 32 + aoff);  // last smem reads

        if (prefetch) {
            __syncthreads();                 // all smem reads of chunk done
            LOAD_STAGE(ch & 1, (ch0 + ch + 2) * 32)
        }

        // register-only MMAs cover the barrier/prefetch window
        #pragma unroll
        for (int mi = 0; mi < 4; mi++)
            #pragma unroll
            for (int ni = 0; ni < 4; ni++)
                mma_fp16(acc[mi][ni], af[mi], &bf[ni >> 1][(ni & 1) * 2]);

        if (!prefetch && ch + 1 < nch) __syncthreads();  // protect stage reuse
    }

    // ---- epilogue: fragment layout -> global fp32 ----
    const int rr = lane >> 2;
    const int cc = (lane & 3) * 2;
    #pragma unroll
    for (int mi = 0; mi < 4; mi++) {
        int grow = bm * 128 + wm + mi * 16 + rr;
        #pragma unroll
        for (int ni = 0; ni < 4; ni++) {
            int gcol = bn * 128 + wn + ni * 8 + cc;
            *(float2*)&C[(size_t)grow * ldc + gcol] =
                make_float2(acc[mi][ni][0], acc[mi][ni][1]);
            *(float2*)&C[(size_t)(grow + 8) * ldc + gcol] =
                make_float2(acc[mi][ni][2], acc[mi][ni][3]);
        }
    }
    #undef LOAD_STAGE
}

// ---- merged logits GEMM: z=0 -> speech/svm, z=1 -> face/fkm --------------
__global__ __launch_bounds__(256, 2) void gemm_logits_k(
    const __half* __restrict__ Sh, const __half* __restrict__ Vh,
    const __half* __restrict__ Fh, const __half* __restrict__ Kh,
    float* __restrict__ C) {
    const int z = blockIdx.z;
    const __half* A = z ? Fh : Sh;
    const __half* B = z ? Kh : Vh;
    float* Cz = C + (size_t)z * N_ROWS * S_ROWS;
    gemm1_body(A, B, Cz, C_DIM, S_ROWS, 0, C_DIM / 32, blockIdx.y, blockIdx.x);
}

// ---- merged recall GEMM with split-K=2: M=16384, partials to g_part ------
__global__ __launch_bounds__(256, 2) void gemm_recall_k(
    const __half* __restrict__ P, const __half* __restrict__ Vt,
    float* __restrict__ part) {
    const int z = blockIdx.z;                       // K half
    float* Cz = part + (size_t)z * 2 * N_ROWS * C_DIM;
    gemm1_body(P, Vt, Cz, S_ROWS, C_DIM, z * 64, 64, blockIdx.y, blockIdx.x);
}

// ---- reduce split-K partials and scatter to the two recall outputs -------
__global__ __launch_bounds__(256) void reduce_recall_k(const float* __restrict__ part,
                                                       float* __restrict__ outS,
                                                       float* __restrict__ outF) {
    const size_t i = ((size_t)blockIdx.x * 256 + threadIdx.x) * 4;  // over 16384*256 floats
    float4 a = *(const float4*)&part[i];
    float4 b = *(const float4*)&part[i + (size_t)2 * N_ROWS * C_DIM];
    a.x += b.x; a.y += b.y; a.z += b.z; a.w += b.w;
    const size_t half = (size_t)N_ROWS * C_DIM;
    if (i < half) *(float4*)&outS[i] = a;
    else          *(float4*)&outF[i - half] = a;
}

// ---------------- launch ---------------------------------------------------
extern "C" void kernel_launch(void* const* d_in, const int* in_sizes, int n_in,
                              void* d_out, int out_size) {
    const float* face   = (const float*)d_in[0];
    const float* speech = (const float*)d_in[1];
    const float* svm    = (const float*)d_in[2];
    const float* fkm    = (const float*)d_in[3];
    float* out = (float*)d_out;

    __half *Sh, *Fh, *Vh, *Kh, *Vth, *Ph;
    float* Part;
    cudaGetSymbolAddress((void**)&Sh, g_Sh);
    cudaGetSymbolAddress((void**)&Fh, g_Fh);
    cudaGetSymbolAddress((void**)&Vh, g_Vh);
    cudaGetSymbolAddress((void**)&Kh, g_Kh);
    cudaGetSymbolAddress((void**)&Vth, g_Vth);
    cudaGetSymbolAddress((void**)&Ph, g_Ph);
    cudaGetSymbolAddress((void**)&Part, g_part);

    const size_t o_se  = 0;
    const size_t o_ser = 2097152;
    const size_t o_fe  = 4194304;
    const size_t o_fer = 6291456;
    const size_t o_sal = 8388608;

    cudaMemcpyAsync(out + o_se, speech, (size_t)N_ROWS * C_DIM * sizeof(float),
                    cudaMemcpyDeviceToDevice, 0);
    cudaMemcpyAsync(out + o_fe, face, (size_t)N_ROWS * C_DIM * sizeof(float),
                    cudaMemcpyDeviceToDevice, 0);

    cudaFuncSetAttribute(gemm_logits_k, cudaFuncAttributeMaxDynamicSharedMemorySize, GEMM_SMEM);
    cudaFuncSetAttribute(gemm_recall_k, cudaFuncAttributeMaxDynamicSharedMemorySize, GEMM_SMEM);

    // prep (3 kernels so gemm_logits_k is the 6th op incl. the 2 memcpys)
    norm_emb_k<<<2 * N_ROWS, 256>>>(speech, face, Sh, Fh);
    norm_mem_k<<<2 * S_ROWS, 256>>>(svm, fkm, Vh, Kh);
    transpose_half_k<<<dim3(C_DIM / 32, S_ROWS / 32), dim3(32, 8)>>>(svm, Vth);

    // merged logits GEMM: [2][8192,4096] = A[8192,256] x B[4096,256]^T
    gemm_logits_k<<<dim3(32, 64, 2), 256, GEMM_SMEM>>>(Sh, Vh, Fh, Kh, out + o_sal);

    // log-softmax (in place) + P = exp(logsm) fp16 over both matrices
    softmax_rows_k<<<2 * N_ROWS, 256>>>(out + o_sal, Ph);

    // merged recall GEMM (M=16384) with split-K=2 -> partials, then reduce
    gemm_recall_k<<<dim3(2, 128, 2), 256, GEMM_SMEM>>>(Ph, Vth, Part);
    reduce_recall_k<<<(2 * N_ROWS * C_DIM) / (256 * 4), 256>>>(Part, out + o_ser, out + o_fer);
}